// round 8
// baseline (speedup 1.0000x reference)
#include <cuda_runtime.h>
#include <math.h>
#include <stdint.h>

// Problem constants
#define BB   16
#define NN   2048
#define CIN  64
#define CC   256
#define MTOT (BB*NN)   // 32768
#define NBLK 16        // NN/128
#define NPAIRS 136     // NBLK*(NBLK+1)/2

// dynamic smem: 4 buffers x 2560 floats + 128 rsc
#define SMEMB ((4*2560 + 128) * 4)

// ---------------- scratch (device globals; no allocation allowed) ----------------
__device__ float g_h[MTOT*CC];
__device__ float g_q[MTOT*CC];
__device__ float g_v[MTOT*CC];
__device__ float g_u[MTOT*CC];
__device__ float g_attn[(size_t)BB*NN*NN];   // 256 MiB energy matrix (raw, no softmax)
__device__ float2 g_stats[MTOT];             // per-row {max, 1/sumexp}
__device__ float g_bnscale[3*CC];
__device__ float g_bnshift[3*CC];

// ---------------- BN precompute ----------------
__global__ void bn_prep(const float* __restrict__ g1, const float* __restrict__ b1,
                        const float* __restrict__ m1, const float* __restrict__ v1,
                        const float* __restrict__ g2, const float* __restrict__ b2,
                        const float* __restrict__ m2, const float* __restrict__ v2,
                        const float* __restrict__ g3, const float* __restrict__ b3,
                        const float* __restrict__ m3, const float* __restrict__ v3,
                        const float* __restrict__ bt)
{
    int c = threadIdx.x;
    float s;
    s = g1[c] * rsqrtf(v1[c] + 1e-5f);
    g_bnscale[c]       = s; g_bnshift[c]       = b1[c] - m1[c]*s;
    s = g2[c] * rsqrtf(v2[c] + 1e-5f);
    g_bnscale[256 + c] = s; g_bnshift[256 + c] = b2[c] - m2[c]*s;
    s = g3[c] * rsqrtf(v3[c] + 1e-5f);
    g_bnscale[512 + c] = s; g_bnshift[512 + c] = (bt[c] - m3[c])*s + b3[c];
}

__device__ __forceinline__ uint32_t cvt_tf32(float x) {
    uint32_t u;
    asm("cvt.rna.tf32.f32 %0, %1;" : "=r"(u) : "f"(x));
    return u;
}

__device__ __forceinline__ float4 cvt4(float4 v) {
    float4 o;
    o.x = __uint_as_float(cvt_tf32(v.x));
    o.y = __uint_as_float(cvt_tf32(v.y));
    o.z = __uint_as_float(cvt_tf32(v.z));
    o.w = __uint_as_float(cvt_tf32(v.w));
    return o;
}

// ---------------- tensor-core tiled GEMM (tf32 mma.sync, register-staged pipe) ----
// C[m,n] = sum_k opA(A)[m,k] * opB(B)[n,k]
// BM=BN=128, BK=16; 256 threads = 8 warps (2x4), warp tile 64x32 = 4x4 m16n8k8.
// smem holds tf32-rounded bits (converted at STS); inner loop = LDS + HMMA only.
//   non-trans operand: [row][k]  stride 20
//   trans operand:     [k][row]  stride 136
// EPI: 0 plain; 1 relu(acc*p0[c]+p1[c]); 2 acc+p0[c];
//      4 p2[r,c] - acc*rscale[r]; A elements are softmaxed ON THE FLY in staging:
//        p = expf(raw - mx[k]) * inv[k]  (stats via p0); rscale from in-CTA colsum;
//      5 symmetric-output: blockIdx.x = upper-tri pair (bi<=bj); store block and,
//        if off-diagonal, its transpose (smem-staged, coalesced);
//      6 fused final: out[b,c,i] = p2[r,c] + relu(acc*p0[c]+p1[c]),
//        stored TRANSPOSED to C ([B,C,N] layout) via smem staging.
template<int EPI, bool ATRANS, bool BTRANS>
__global__ __launch_bounds__(256, 2)
void gemm_tc(const float* __restrict__ A, const float* __restrict__ B,
             float* __restrict__ C, int K,
             int lda, int ldb, int ldc,
             long long sA, long long sB, long long sC,
             const float* __restrict__ p0, const float* __restrict__ p1,
             const float* __restrict__ p2)
{
    extern __shared__ float smem[];
    float* As0 = smem;
    float* As1 = smem + 2560;
    float* Bs0 = smem + 2 * 2560;
    float* Bs1 = smem + 3 * 2560;
    float* rsc = smem + 4 * 2560;   // EPI4: per-row 1/(eps+colsum)

    const int z = blockIdx.z;
    A += (long long)z * sA;
    B += (long long)z * sB;

    const int t    = threadIdx.x;
    const int lane = t & 31;
    const int wid  = t >> 5;
    const int wm   = wid >> 2;      // 0..1
    const int wn   = wid & 3;       // 0..3
    const int grp  = lane >> 2;     // 0..7
    const int qid  = lane & 3;      // 0..3

    int m0, n0;
    if (EPI == 5) {
        int rem = blockIdx.x, bi = 0;
        while (rem >= NBLK - bi) { rem -= NBLK - bi; bi++; }
        m0 = bi * 128;
        n0 = (bi + rem) * 128;
    } else {
        m0 = blockIdx.y * 128;
        n0 = blockIdx.x * 128;
    }

    const int idx0 = t, idx1 = t + 256;

    // per-thread global base pointers and per-16-k strides
    const long long aStep = ATRANS ? (long long)lda * 16 : 16;
    const long long bStep = BTRANS ? (long long)ldb * 16 : 16;
    const float* aP0 = A + (ATRANS ? (long long)(idx0 >> 5) * lda + m0 + (idx0 & 31) * 4
                                   : (long long)(m0 + (idx0 >> 2)) * lda + (idx0 & 3) * 4);
    const float* aP1 = A + (ATRANS ? (long long)(idx1 >> 5) * lda + m0 + (idx1 & 31) * 4
                                   : (long long)(m0 + (idx1 >> 2)) * lda + (idx1 & 3) * 4);
    const float* bP0 = B + (BTRANS ? (long long)(idx0 >> 5) * ldb + n0 + (idx0 & 31) * 4
                                   : (long long)(n0 + (idx0 >> 2)) * ldb + (idx0 & 3) * 4);
    const float* bP1 = B + (BTRANS ? (long long)(idx1 >> 5) * ldb + n0 + (idx1 & 31) * 4
                                   : (long long)(n0 + (idx1 >> 2)) * ldb + (idx1 & 3) * 4);

    // EPI4: per-batch softmax stats (row of A in k-dimension)
    const float2* stf = (EPI == 4) ? ((const float2*)p0 + (long long)z * NN) : nullptr;

    // smem store offsets (fixed per thread)
    const int aS0 = ATRANS ? (idx0 >> 5) * 136 + (idx0 & 31) * 4
                           : (idx0 >> 2) * 20  + (idx0 & 3)  * 4;
    const int aS1 = ATRANS ? (idx1 >> 5) * 136 + (idx1 & 31) * 4
                           : (idx1 >> 2) * 20  + (idx1 & 3)  * 4;
    const int bS0 = BTRANS ? (idx0 >> 5) * 136 + (idx0 & 31) * 4
                           : (idx0 >> 2) * 20  + (idx0 & 3)  * 4;
    const int bS1 = BTRANS ? (idx1 >> 5) * 136 + (idx1 & 31) * 4
                           : (idx1 >> 2) * 20  + (idx1 & 3)  * 4;

    float acc[4][4][4];
#pragma unroll
    for (int i = 0; i < 4; i++)
#pragma unroll
        for (int j = 0; j < 4; j++)
#pragma unroll
            for (int e = 0; e < 4; e++) acc[i][j][e] = 0.f;

    float4 stA0, stA1, stB0, stB1;            // staging registers
    float2 f0, f1;                            // EPI4: stats for the two staged k-rows
    float colacc[4] = {0.f, 0.f, 0.f, 0.f};   // EPI4: partial column sums of attn

#define LDG_TILE(kit)                                                    \
    {                                                                    \
        long long ao = (long long)(kit) * aStep;                         \
        long long bo = (long long)(kit) * bStep;                         \
        stA0 = *(const float4*)(aP0 + ao);                               \
        stA1 = *(const float4*)(aP1 + ao);                               \
        stB0 = *(const float4*)(bP0 + bo);                               \
        stB1 = *(const float4*)(bP1 + bo);                               \
        if (EPI == 4) {                                                  \
            f0 = stf[(t >> 5) + 16 * (kit)];                             \
            f1 = stf[(t >> 5) + 8 + 16 * (kit)];                         \
        }                                                                \
    }

#define STS_TILE(Aw, Bw)                                                 \
    {                                                                    \
        if (EPI == 4) {                                                  \
            stA0.x = __expf(stA0.x - f0.x) * f0.y;                       \
            stA0.y = __expf(stA0.y - f0.x) * f0.y;                       \
            stA0.z = __expf(stA0.z - f0.x) * f0.y;                       \
            stA0.w = __expf(stA0.w - f0.x) * f0.y;                       \
            stA1.x = __expf(stA1.x - f1.x) * f1.y;                       \
            stA1.y = __expf(stA1.y - f1.x) * f1.y;                       \
            stA1.z = __expf(stA1.z - f1.x) * f1.y;                       \
            stA1.w = __expf(stA1.w - f1.x) * f1.y;                       \
            colacc[0] += stA0.x + stA1.x;                                \
            colacc[1] += stA0.y + stA1.y;                                \
            colacc[2] += stA0.z + stA1.z;                                \
            colacc[3] += stA0.w + stA1.w;                                \
        }                                                                \
        *(float4*)&(Aw)[aS0] = cvt4(stA0);                               \
        *(float4*)&(Aw)[aS1] = cvt4(stA1);                               \
        *(float4*)&(Bw)[bS0] = cvt4(stB0);                               \
        *(float4*)&(Bw)[bS1] = cvt4(stB1);                               \
    }

    // prologue
    LDG_TILE(0)
    STS_TILE(As0, Bs0)
    __syncthreads();

    const int kIters = K / 16;
    for (int kit = 0, buf = 0; kit < kIters; kit++, buf ^= 1) {
        const bool have_next = (kit + 1) < kIters;
        if (have_next) LDG_TILE(kit + 1)

        const float* Ab = buf ? As1 : As0;
        const float* Bb = buf ? Bs1 : Bs0;
#pragma unroll
        for (int ks = 0; ks < 16; ks += 8) {
            uint32_t a[4][4], b[4][2];
#pragma unroll
            for (int i = 0; i < 4; i++) {
                int rb = wm * 64 + i * 16 + grp;
                if (!ATRANS) {
                    a[i][0] = __float_as_uint(Ab[(rb    ) * 20 + ks + qid]);
                    a[i][1] = __float_as_uint(Ab[(rb + 8) * 20 + ks + qid]);
                    a[i][2] = __float_as_uint(Ab[(rb    ) * 20 + ks + 4 + qid]);
                    a[i][3] = __float_as_uint(Ab[(rb + 8) * 20 + ks + 4 + qid]);
                } else {
                    a[i][0] = __float_as_uint(Ab[(ks + qid    ) * 136 + rb]);
                    a[i][1] = __float_as_uint(Ab[(ks + qid    ) * 136 + rb + 8]);
                    a[i][2] = __float_as_uint(Ab[(ks + qid + 4) * 136 + rb]);
                    a[i][3] = __float_as_uint(Ab[(ks + qid + 4) * 136 + rb + 8]);
                }
            }
#pragma unroll
            for (int j = 0; j < 4; j++) {
                int nb = wn * 32 + j * 8 + grp;
                if (!BTRANS) {
                    b[j][0] = __float_as_uint(Bb[nb * 20 + ks + qid]);
                    b[j][1] = __float_as_uint(Bb[nb * 20 + ks + 4 + qid]);
                } else {
                    b[j][0] = __float_as_uint(Bb[(ks + qid    ) * 136 + nb]);
                    b[j][1] = __float_as_uint(Bb[(ks + qid + 4) * 136 + nb]);
                }
            }
#pragma unroll
            for (int i = 0; i < 4; i++)
#pragma unroll
                for (int j = 0; j < 4; j++) {
                    asm volatile(
                        "mma.sync.aligned.m16n8k8.row.col.f32.tf32.tf32.f32 "
                        "{%0,%1,%2,%3}, {%4,%5,%6,%7}, {%8,%9}, {%0,%1,%2,%3};\n"
                        : "+f"(acc[i][j][0]), "+f"(acc[i][j][1]),
                          "+f"(acc[i][j][2]), "+f"(acc[i][j][3])
                        : "r"(a[i][0]), "r"(a[i][1]), "r"(a[i][2]), "r"(a[i][3]),
                          "r"(b[j][0]), "r"(b[j][1]));
                }
        }
        if (have_next) {
            if (buf) STS_TILE(As0, Bs0)
            else     STS_TILE(As1, Bs1)
        }
        __syncthreads();
    }
#undef LDG_TILE
#undef STS_TILE

    // ---- EPI4: reduce column sums -> rscale in smem ----
    if (EPI == 4) {
        float* red = As0;      // 8 groups x 128 columns (first 1024 floats)
        const int g  = t >> 5;
        const int cq = (t & 31) * 4;
        red[g * 128 + cq + 0] = colacc[0];
        red[g * 128 + cq + 1] = colacc[1];
        red[g * 128 + cq + 2] = colacc[2];
        red[g * 128 + cq + 3] = colacc[3];
        __syncthreads();
        if (t < 128) {
            float s = 0.f;
#pragma unroll
            for (int gg = 0; gg < 8; gg++) s += red[gg * 128 + t];
            rsc[t] = 1.f / (1e-9f + s);
        }
        __syncthreads();
    }

    float* Cz = C + (long long)z * sC;

    // ---- epilogue: direct store (all EPIs except 6) ----
    if (EPI != 6) {
#pragma unroll
        for (int i = 0; i < 4; i++) {
            int r0 = m0 + wm * 64 + i * 16 + grp;
            int r1 = r0 + 8;
#pragma unroll
            for (int j = 0; j < 4; j++) {
                int c = n0 + wn * 32 + j * 8 + qid * 2;
                float d0 = acc[i][j][0], d1 = acc[i][j][1];
                float d2 = acc[i][j][2], d3 = acc[i][j][3];
                float2 o0, o1;
                if (EPI == 0 || EPI == 5) {
                    o0 = make_float2(d0, d1);
                    o1 = make_float2(d2, d3);
                } else if (EPI == 1) {
                    float s0 = p0[c], s1 = p0[c+1], h0 = p1[c], h1 = p1[c+1];
                    o0.x = fmaxf(d0 * s0 + h0, 0.f);
                    o0.y = fmaxf(d1 * s1 + h1, 0.f);
                    o1.x = fmaxf(d2 * s0 + h0, 0.f);
                    o1.y = fmaxf(d3 * s1 + h1, 0.f);
                } else if (EPI == 2) {
                    float h0 = p0[c], h1 = p0[c+1];
                    o0 = make_float2(d0 + h0, d1 + h1);
                    o1 = make_float2(d2 + h0, d3 + h1);
                } else { // EPI == 4 : u = h - acc*rscale[row]
                    float rsa = rsc[r0 - m0];
                    float rsb = rsc[r1 - m0];
                    const float* hpz = p2 + (long long)z * sC;
                    o0.x = hpz[(long long)r0 * ldc + c    ] - d0 * rsa;
                    o0.y = hpz[(long long)r0 * ldc + c + 1] - d1 * rsa;
                    o1.x = hpz[(long long)r1 * ldc + c    ] - d2 * rsb;
                    o1.y = hpz[(long long)r1 * ldc + c + 1] - d3 * rsb;
                }
                *(float2*)&Cz[(long long)r0 * ldc + c] = o0;
                *(float2*)&Cz[(long long)r1 * ldc + c] = o1;
            }
        }
    }

    // ---- EPI5 off-diagonal: mirrored (transposed) store via smem staging ----
    if (EPI == 5 && m0 != n0) {
        float* sm_t = smem;   // 64 x 132 floats = 8448 <= 10240 available
#pragma unroll
        for (int half = 0; half < 2; half++) {
            __syncthreads();
            if (wm == half) {
#pragma unroll
                for (int i = 0; i < 4; i++) {
                    int rl = i * 16 + grp;
#pragma unroll
                    for (int j = 0; j < 4; j++) {
                        int c = wn * 32 + j * 8 + qid * 2;
                        sm_t[rl * 132 + c]           = acc[i][j][0];
                        sm_t[rl * 132 + c + 1]       = acc[i][j][1];
                        sm_t[(rl + 8) * 132 + c]     = acc[i][j][2];
                        sm_t[(rl + 8) * 132 + c + 1] = acc[i][j][3];
                    }
                }
            }
            __syncthreads();
            // write C[n0+c][m0 + half*64 + 0..63], coalesced float4
            int c   = t >> 1;
            int seg = (t & 1) * 32;
            float* dst = Cz + (long long)(n0 + c) * ldc + m0 + half * 64 + seg;
#pragma unroll
            for (int s = 0; s < 32; s += 4) {
                float4 o;
                o.x = sm_t[(seg + s + 0) * 132 + c];
                o.y = sm_t[(seg + s + 1) * 132 + c];
                o.z = sm_t[(seg + s + 2) * 132 + c];
                o.w = sm_t[(seg + s + 3) * 132 + c];
                *(float4*)(dst + s) = o;
            }
        }
    }

    // ---- EPI6: out[b,c,i] = h[r,c] + relu(acc*scale+shift), transposed store ----
    if (EPI == 6) {
        // transform acc in place to final output values
#pragma unroll
        for (int i = 0; i < 4; i++) {
            int r0 = m0 + wm * 64 + i * 16 + grp;
            int r1 = r0 + 8;
#pragma unroll
            for (int j = 0; j < 4; j++) {
                int c = n0 + wn * 32 + j * 8 + qid * 2;
                float s0 = p0[c], s1 = p0[c+1], h0 = p1[c], h1 = p1[c+1];
                acc[i][j][0] = fmaxf(acc[i][j][0] * s0 + h0, 0.f) + p2[(long long)r0 * ldc + c    ];
                acc[i][j][1] = fmaxf(acc[i][j][1] * s1 + h1, 0.f) + p2[(long long)r0 * ldc + c + 1];
                acc[i][j][2] = fmaxf(acc[i][j][2] * s0 + h0, 0.f) + p2[(long long)r1 * ldc + c    ];
                acc[i][j][3] = fmaxf(acc[i][j][3] * s1 + h1, 0.f) + p2[(long long)r1 * ldc + c + 1];
            }
        }
        const int zb = m0 >> 11;          // batch index (m0 / NN)
        const int ib = m0 & (NN - 1);     // token base within batch
        float* outz = C + ((long long)zb * CC + n0) * NN;
        float* sm_t = smem;               // 64 x 132 floats
#pragma unroll
        for (int half = 0; half < 2; half++) {
            __syncthreads();
            if (wm == half) {
#pragma unroll
                for (int i = 0; i < 4; i++) {
                    int rl = i * 16 + grp;
#pragma unroll
                    for (int j = 0; j < 4; j++) {
                        int c = wn * 32 + j * 8 + qid * 2;
                        sm_t[rl * 132 + c]           = acc[i][j][0];
                        sm_t[rl * 132 + c + 1]       = acc[i][j][1];
                        sm_t[(rl + 8) * 132 + c]     = acc[i][j][2];
                        sm_t[(rl + 8) * 132 + c + 1] = acc[i][j][3];
                    }
                }
            }
            __syncthreads();
            // write out[(zb*CC + n0 + c)][ib + half*64 + 0..63], coalesced float4
            int c   = t >> 1;
            int seg = (t & 1) * 32;
            float* dst = outz + (long long)c * NN + ib + half * 64 + seg;
#pragma unroll
            for (int s = 0; s < 32; s += 4) {
                float4 o;
                o.x = sm_t[(seg + s + 0) * 132 + c];
                o.y = sm_t[(seg + s + 1) * 132 + c];
                o.z = sm_t[(seg + s + 2) * 132 + c];
                o.w = sm_t[(seg + s + 3) * 132 + c];
                *(float4*)(dst + s) = o;
            }
        }
    }
}

// ---------------- per-row stats of energy: {max, 1/sum(exp)} ---------------------
// Identical reduction structure to the old softmax (bitwise-same mx and sum).
__global__ void rowstats(const float* __restrict__ e, float2* __restrict__ st)
{
    __shared__ float red[256];
    const float* p = e + (long long)blockIdx.x * NN;
    const int t = threadIdx.x;
    float v[8];
    float mx = -1e30f;
#pragma unroll
    for (int i = 0; i < 8; i++) { v[i] = p[t + i*256]; mx = fmaxf(mx, v[i]); }
    red[t] = mx; __syncthreads();
    for (int s = 128; s > 0; s >>= 1) {
        if (t < s) red[t] = fmaxf(red[t], red[t + s]);
        __syncthreads();
    }
    mx = red[0]; __syncthreads();
    float sum = 0.f;
#pragma unroll
    for (int i = 0; i < 8; i++) { sum += __expf(v[i] - mx); }
    red[t] = sum; __syncthreads();
    for (int s = 128; s > 0; s >>= 1) {
        if (t < s) red[t] += red[t + s];
        __syncthreads();
    }
    if (t == 0) st[blockIdx.x] = make_float2(mx, 1.f / red[0]);
}

// ==================================================================================
extern "C" void kernel_launch(void* const* d_in, const int* in_sizes, int n_in,
                              void* d_out, int out_size)
{
    const float* x   = (const float*)d_in[0];
    const float* w1  = (const float*)d_in[1];
    const float* w2  = (const float*)d_in[2];
    const float* wqk = (const float*)d_in[3];
    const float* wv  = (const float*)d_in[4];
    const float* bv  = (const float*)d_in[5];
    const float* wt  = (const float*)d_in[6];
    const float* bt  = (const float*)d_in[7];
    const float* bn1g = (const float*)d_in[8],  *bn1b = (const float*)d_in[9];
    const float* bn1m = (const float*)d_in[10], *bn1v = (const float*)d_in[11];
    const float* bn2g = (const float*)d_in[12], *bn2b = (const float*)d_in[13];
    const float* bn2m = (const float*)d_in[14], *bn2v = (const float*)d_in[15];
    const float* bn3g = (const float*)d_in[16], *bn3b = (const float*)d_in[17];
    const float* bn3m = (const float*)d_in[18], *bn3v = (const float*)d_in[19];

    float *h, *q, *v, *u, *attn, *bns, *bnh;
    float2 *stats;
    cudaGetSymbolAddress((void**)&h, g_h);
    cudaGetSymbolAddress((void**)&q, g_q);
    cudaGetSymbolAddress((void**)&v, g_v);
    cudaGetSymbolAddress((void**)&u, g_u);
    cudaGetSymbolAddress((void**)&attn, g_attn);
    cudaGetSymbolAddress((void**)&stats, g_stats);
    cudaGetSymbolAddress((void**)&bns, g_bnscale);
    cudaGetSymbolAddress((void**)&bnh, g_bnshift);

    bn_prep<<<1, 256>>>(bn1g, bn1b, bn1m, bn1v,
                        bn2g, bn2b, bn2m, bn2v,
                        bn3g, bn3b, bn3m, bn3v, bt);

    // h1 = relu(bn1(x @ w1^T))   (into q as temp)
    gemm_tc<1, false, false><<<dim3(CC/128, MTOT/128, 1), 256, SMEMB>>>(
        x, w1, q, CIN, CIN, CIN, CC, 0, 0, 0, bns, bnh, nullptr);

    // h = relu(bn2(h1 @ w2^T))
    gemm_tc<1, false, false><<<dim3(CC/128, MTOT/128, 1), 256, SMEMB>>>(
        q, w2, h, CC, CC, CC, CC, 0, 0, 0, bns + 256, bnh + 256, nullptr);

    // q = h @ wqk^T
    gemm_tc<0, false, false><<<dim3(CC/128, MTOT/128, 1), 256, SMEMB>>>(
        h, wqk, q, CC, CC, CC, CC, 0, 0, 0, nullptr, nullptr, nullptr);

    // v = h @ wv^T + bv
    gemm_tc<2, false, false><<<dim3(CC/128, MTOT/128, 1), 256, SMEMB>>>(
        h, wv, v, CC, CC, CC, CC, 0, 0, 0, bv, nullptr, nullptr);

    // energy[b,i,j] = q[b,i,:] . q[b,j,:]   (batched, SYMMETRIC: upper-tri blocks)
    gemm_tc<5, false, false><<<dim3(NPAIRS, 1, BB), 256, SMEMB>>>(
        q, q, attn, CC, CC, CC, NN,
        (long long)NN*CC, (long long)NN*CC, (long long)NN*NN,
        nullptr, nullptr, nullptr);

    // per-row softmax stats (no attn materialization)
    rowstats<<<MTOT, 256>>>(attn, stats);

    // u[b,j,c] = h - (sum_i p[i,j] v[i,c]) / (eps + sum_i p[i,j]),
    // p = softmax(energy) computed on the fly in A staging; colsum fused in-CTA
    gemm_tc<4, true, true><<<dim3(CC/128, NN/128, BB), 256, SMEMB>>>(
        attn, v, u, NN, NN, CC, CC,
        (long long)NN*NN, (long long)NN*CC, (long long)NN*CC,
        (const float*)stats, nullptr, h);

    // out[b,c,i] = h + relu(bn3(u @ wt^T + bt))   (fused, transposed store)
    gemm_tc<6, false, false><<<dim3(CC/128, MTOT/128, 1), 256, SMEMB>>>(
        u, wt, (float*)d_out, CC, CC, CC, CC, 0, 0, 0, bns + 512, bnh + 512, h);
}

// round 9
// speedup vs baseline: 1.0776x; 1.0776x over previous
#include <cuda_runtime.h>
#include <math.h>
#include <stdint.h>

// Problem constants
#define BB   16
#define NN   2048
#define CIN  64
#define CC   256
#define MTOT (BB*NN)   // 32768
#define NBLK 16        // NN/128
#define NPAIRS 136     // NBLK*(NBLK+1)/2

// register-staged GEMM smem (x_r only): 4 buffers x 2560 + 128
#define SMEMB ((4*2560 + 128) * 4)
// cp.async GEMM smem: 4 stages x (2560 A + 2560 B)
#define SMEMCA (8 * 2560 * 4)

// ---------------- scratch (device globals; no allocation allowed) ----------------
__device__ float g_h[MTOT*CC];
__device__ float g_q[MTOT*CC];
__device__ float g_v[MTOT*CC];
__device__ float g_u[MTOT*CC];
__device__ float g_attn[(size_t)BB*NN*NN];   // 256 MiB
__device__ float g_xr[MTOT*CIN];             // rounded x
__device__ float g_wr[5*CC*CC];              // rounded w1(16K pad to 64K),w2,wqk,wv,wt
__device__ float g_bnscale[3*CC];
__device__ float g_bnshift[3*CC];

// ---------------- BN precompute ----------------
__global__ void bn_prep(const float* __restrict__ g1, const float* __restrict__ b1,
                        const float* __restrict__ m1, const float* __restrict__ v1,
                        const float* __restrict__ g2, const float* __restrict__ b2,
                        const float* __restrict__ m2, const float* __restrict__ v2,
                        const float* __restrict__ g3, const float* __restrict__ b3,
                        const float* __restrict__ m3, const float* __restrict__ v3,
                        const float* __restrict__ bt)
{
    int c = threadIdx.x;
    float s;
    s = g1[c] * rsqrtf(v1[c] + 1e-5f);
    g_bnscale[c]       = s; g_bnshift[c]       = b1[c] - m1[c]*s;
    s = g2[c] * rsqrtf(v2[c] + 1e-5f);
    g_bnscale[256 + c] = s; g_bnshift[256 + c] = b2[c] - m2[c]*s;
    s = g3[c] * rsqrtf(v3[c] + 1e-5f);
    g_bnscale[512 + c] = s; g_bnshift[512 + c] = (bt[c] - m3[c])*s + b3[c];
}

__device__ __forceinline__ uint32_t cvt_tf32(float x) {
    uint32_t u;
    asm("cvt.rna.tf32.f32 %0, %1;" : "=r"(u) : "f"(x));
    return u;
}
__device__ __forceinline__ float cvt1(float x) { return __uint_as_float(cvt_tf32(x)); }

__device__ __forceinline__ float4 cvt4(float4 v) {
    float4 o;
    o.x = cvt1(v.x); o.y = cvt1(v.y); o.z = cvt1(v.z); o.w = cvt1(v.w);
    return o;
}

__device__ __forceinline__ uint32_t smem_u32(const void* p) {
    return (uint32_t)__cvta_generic_to_shared(p);
}
__device__ __forceinline__ void cp_async16(uint32_t dst, const void* src) {
    asm volatile("cp.async.cg.shared.global [%0], [%1], 16;\n" :: "r"(dst), "l"(src));
}

// ---------------- elementwise tf32 pre-round ----------------
__global__ void round_arr(float* __restrict__ dst, const float* __restrict__ src, int n)
{
    int i = (blockIdx.x * 256 + threadIdx.x) * 4;
    if (i < n) *(float4*)&dst[i] = cvt4(*(const float4*)&src[i]);
}

// ================= cp.async 4-stage GEMM (operands pre-rounded tf32) =============
// C[m,n] = sum_k A[m*lda+k] * B[n*ldb+k]   (both operands K-last)
// BM=BN=128, BK=16; 256 threads = 8 warps, warp 64x32 = 4x4 m16n8k8.
// EPI: 1 cvt(relu(acc*p0[c]+p1[c]));  2 cvt(acc+p0[c]);  3 cvt(acc);
//      7 relu(acc*p0[c]+p1[c]) raw;   5 raw symmetric (pair-indexed + mirror)
template<int EPI>
__global__ __launch_bounds__(256, 2)
void gemm_ca(const float* __restrict__ A, const float* __restrict__ B,
             float* __restrict__ C, int K,
             int lda, int ldb, int ldc,
             long long sA, long long sB, long long sC,
             const float* __restrict__ p0, const float* __restrict__ p1)
{
    extern __shared__ float smem[];   // As: [s*2560], Bs: [10240 + s*2560]

    const int z = blockIdx.z;
    A += (long long)z * sA;
    B += (long long)z * sB;

    const int t    = threadIdx.x;
    const int lane = t & 31;
    const int wid  = t >> 5;
    const int wm   = wid >> 2;
    const int wn   = wid & 3;
    const int grp  = lane >> 2;
    const int qid  = lane & 3;

    int m0, n0;
    if (EPI == 5) {
        int rem = blockIdx.x, bi = 0;
        while (rem >= NBLK - bi) { rem -= NBLK - bi; bi++; }
        m0 = bi * 128;
        n0 = (bi + rem) * 128;
    } else {
        m0 = blockIdx.y * 128;
        n0 = blockIdx.x * 128;
    }

    const int row = t >> 2, kq = t & 3;
    const float* aSrc0 = A + (long long)(m0 + row) * lda + kq * 4;
    const float* aSrc1 = aSrc0 + (long long)64 * lda;
    const float* bSrc0 = B + (long long)(n0 + row) * ldb + kq * 4;
    const float* bSrc1 = bSrc0 + (long long)64 * ldb;
    const int off0 = row * 20 + kq * 4;
    const int off1 = off0 + 64 * 20;

#define ISSUE(kit)                                                            \
    {                                                                         \
        int s_ = (kit) & 3;                                                   \
        float* As_ = smem + s_ * 2560;                                        \
        float* Bs_ = smem + 10240 + s_ * 2560;                                \
        long long ko_ = (long long)(kit) * 16;                                \
        cp_async16(smem_u32(As_ + off0), aSrc0 + ko_);                        \
        cp_async16(smem_u32(As_ + off1), aSrc1 + ko_);                        \
        cp_async16(smem_u32(Bs_ + off0), bSrc0 + ko_);                        \
        cp_async16(smem_u32(Bs_ + off1), bSrc1 + ko_);                        \
        asm volatile("cp.async.commit_group;\n");                             \
    }

    float acc[4][4][4];
#pragma unroll
    for (int i = 0; i < 4; i++)
#pragma unroll
        for (int j = 0; j < 4; j++)
#pragma unroll
            for (int e = 0; e < 4; e++) acc[i][j][e] = 0.f;

    const int kIters = K / 16;
    if (0 < kIters) ISSUE(0)
    if (1 < kIters) ISSUE(1)
    if (2 < kIters) ISSUE(2)

    for (int kit = 0; kit < kIters; kit++) {
        int rem = kIters - 1 - kit;
        if (rem >= 2)      asm volatile("cp.async.wait_group 2;\n");
        else if (rem == 1) asm volatile("cp.async.wait_group 1;\n");
        else               asm volatile("cp.async.wait_group 0;\n");
        __syncthreads();
        if (kit + 3 < kIters) ISSUE(kit + 3)

        const float* Ab = smem + (kit & 3) * 2560;
        const float* Bb = smem + 10240 + (kit & 3) * 2560;
#pragma unroll
        for (int ks = 0; ks < 16; ks += 8) {
            uint32_t a[4][4], b[4][2];
#pragma unroll
            for (int i = 0; i < 4; i++) {
                int rb = wm * 64 + i * 16 + grp;
                a[i][0] = __float_as_uint(Ab[(rb    ) * 20 + ks + qid]);
                a[i][1] = __float_as_uint(Ab[(rb + 8) * 20 + ks + qid]);
                a[i][2] = __float_as_uint(Ab[(rb    ) * 20 + ks + 4 + qid]);
                a[i][3] = __float_as_uint(Ab[(rb + 8) * 20 + ks + 4 + qid]);
            }
#pragma unroll
            for (int j = 0; j < 4; j++) {
                int nb = wn * 32 + j * 8 + grp;
                b[j][0] = __float_as_uint(Bb[nb * 20 + ks + qid]);
                b[j][1] = __float_as_uint(Bb[nb * 20 + ks + 4 + qid]);
            }
#pragma unroll
            for (int i = 0; i < 4; i++)
#pragma unroll
                for (int j = 0; j < 4; j++) {
                    asm volatile(
                        "mma.sync.aligned.m16n8k8.row.col.f32.tf32.tf32.f32 "
                        "{%0,%1,%2,%3}, {%4,%5,%6,%7}, {%8,%9}, {%0,%1,%2,%3};\n"
                        : "+f"(acc[i][j][0]), "+f"(acc[i][j][1]),
                          "+f"(acc[i][j][2]), "+f"(acc[i][j][3])
                        : "r"(a[i][0]), "r"(a[i][1]), "r"(a[i][2]), "r"(a[i][3]),
                          "r"(b[j][0]), "r"(b[j][1]));
                }
        }
    }
#undef ISSUE
    __syncthreads();

    // ---- epilogue ----
    float* Cz = C + (long long)z * sC;
#pragma unroll
    for (int i = 0; i < 4; i++) {
        int r0 = m0 + wm * 64 + i * 16 + grp;
        int r1 = r0 + 8;
#pragma unroll
        for (int j = 0; j < 4; j++) {
            int c = n0 + wn * 32 + j * 8 + qid * 2;
            float d0 = acc[i][j][0], d1 = acc[i][j][1];
            float d2 = acc[i][j][2], d3 = acc[i][j][3];
            float2 o0, o1;
            if (EPI == 5) {
                o0 = make_float2(d0, d1);
                o1 = make_float2(d2, d3);
            } else if (EPI == 3) {
                o0 = make_float2(cvt1(d0), cvt1(d1));
                o1 = make_float2(cvt1(d2), cvt1(d3));
            } else if (EPI == 1 || EPI == 7) {
                float s0 = p0[c], s1 = p0[c+1], h0 = p1[c], h1 = p1[c+1];
                o0.x = fmaxf(d0 * s0 + h0, 0.f);
                o0.y = fmaxf(d1 * s1 + h1, 0.f);
                o1.x = fmaxf(d2 * s0 + h0, 0.f);
                o1.y = fmaxf(d3 * s1 + h1, 0.f);
                if (EPI == 1) {
                    o0.x = cvt1(o0.x); o0.y = cvt1(o0.y);
                    o1.x = cvt1(o1.x); o1.y = cvt1(o1.y);
                }
            } else { // EPI == 2
                float h0 = p0[c], h1 = p0[c+1];
                o0 = make_float2(cvt1(d0 + h0), cvt1(d1 + h1));
                o1 = make_float2(cvt1(d2 + h0), cvt1(d3 + h1));
            }
            *(float2*)&Cz[(long long)r0 * ldc + c] = o0;
            *(float2*)&Cz[(long long)r1 * ldc + c] = o1;
        }
    }

    // ---- EPI5 off-diagonal: mirrored (transposed) store via smem staging ----
    if (EPI == 5 && m0 != n0) {
        float* sm_t = smem;   // 64 x 132 floats
#pragma unroll
        for (int half = 0; half < 2; half++) {
            __syncthreads();
            if (wm == half) {
#pragma unroll
                for (int i = 0; i < 4; i++) {
                    int rl = i * 16 + grp;
#pragma unroll
                    for (int j = 0; j < 4; j++) {
                        int c = wn * 32 + j * 8 + qid * 2;
                        sm_t[rl * 132 + c]           = acc[i][j][0];
                        sm_t[rl * 132 + c + 1]       = acc[i][j][1];
                        sm_t[(rl + 8) * 132 + c]     = acc[i][j][2];
                        sm_t[(rl + 8) * 132 + c + 1] = acc[i][j][3];
                    }
                }
            }
            __syncthreads();
            int c   = t >> 1;
            int seg = (t & 1) * 32;
            float* dst = Cz + (long long)(n0 + c) * ldc + m0 + half * 64 + seg;
#pragma unroll
            for (int s = 0; s < 32; s += 4) {
                float4 o;
                o.x = sm_t[(seg + s + 0) * 132 + c];
                o.y = sm_t[(seg + s + 1) * 132 + c];
                o.z = sm_t[(seg + s + 2) * 132 + c];
                o.w = sm_t[(seg + s + 3) * 132 + c];
                *(float4*)(dst + s) = o;
            }
        }
    }
}

// ======= register-staged GEMM for x_r (EPI4): attn^T @ v with fused colsum =======
// A trans [k][m] (attn, pre-rounded), B trans [k][n] (v, pre-rounded).
// u[r,c] = cvt( h[r,c] - acc * rscale[r] ),  rscale from in-CTA column sums.
__global__ __launch_bounds__(256, 2)
void gemm_xr(const float* __restrict__ A, const float* __restrict__ B,
             float* __restrict__ C, int K,
             int lda, int ldb, int ldc,
             long long sA, long long sB, long long sC,
             const float* __restrict__ p2)
{
    extern __shared__ float smem[];
    float* As0 = smem;
    float* As1 = smem + 2560;
    float* Bs0 = smem + 2 * 2560;
    float* Bs1 = smem + 3 * 2560;
    float* rsc = smem + 4 * 2560;

    const int z = blockIdx.z;
    A += (long long)z * sA;
    B += (long long)z * sB;

    const int t    = threadIdx.x;
    const int lane = t & 31;
    const int wid  = t >> 5;
    const int wm   = wid >> 2;
    const int wn   = wid & 3;
    const int grp  = lane >> 2;
    const int qid  = lane & 3;
    const int m0   = blockIdx.y * 128;
    const int n0   = blockIdx.x * 128;

    const int idx0 = t, idx1 = t + 256;
    const long long aStep = (long long)lda * 16;
    const long long bStep = (long long)ldb * 16;
    const float* aP0 = A + (long long)(idx0 >> 5) * lda + m0 + (idx0 & 31) * 4;
    const float* aP1 = A + (long long)(idx1 >> 5) * lda + m0 + (idx1 & 31) * 4;
    const float* bP0 = B + (long long)(idx0 >> 5) * ldb + n0 + (idx0 & 31) * 4;
    const float* bP1 = B + (long long)(idx1 >> 5) * ldb + n0 + (idx1 & 31) * 4;
    const int aS0 = (idx0 >> 5) * 136 + (idx0 & 31) * 4;
    const int aS1 = (idx1 >> 5) * 136 + (idx1 & 31) * 4;

    float acc[4][4][4];
#pragma unroll
    for (int i = 0; i < 4; i++)
#pragma unroll
        for (int j = 0; j < 4; j++)
#pragma unroll
            for (int e = 0; e < 4; e++) acc[i][j][e] = 0.f;

    float4 stA0, stA1, stB0, stB1;
    float colacc[4] = {0.f, 0.f, 0.f, 0.f};

#define LDG_TILE(kit)                                                    \
    {                                                                    \
        long long ao = (long long)(kit) * aStep;                         \
        long long bo = (long long)(kit) * bStep;                         \
        stA0 = *(const float4*)(aP0 + ao);                               \
        stA1 = *(const float4*)(aP1 + ao);                               \
        stB0 = *(const float4*)(bP0 + bo);                               \
        stB1 = *(const float4*)(bP1 + bo);                               \
    }

#define STS_TILE(Aw, Bw)                                                 \
    {                                                                    \
        colacc[0] += stA0.x + stA1.x;                                    \
        colacc[1] += stA0.y + stA1.y;                                    \
        colacc[2] += stA0.z + stA1.z;                                    \
        colacc[3] += stA0.w + stA1.w;                                    \
        *(float4*)&(Aw)[aS0] = stA0;                                     \
        *(float4*)&(Aw)[aS1] = stA1;                                     \
        *(float4*)&(Bw)[aS0] = stB0;                                     \
        *(float4*)&(Bw)[aS1] = stB1;                                     \
    }

    LDG_TILE(0)
    STS_TILE(As0, Bs0)
    __syncthreads();

    const int kIters = K / 16;
    for (int kit = 0, buf = 0; kit < kIters; kit++, buf ^= 1) {
        const bool have_next = (kit + 1) < kIters;
        if (have_next) LDG_TILE(kit + 1)

        const float* Ab = buf ? As1 : As0;
        const float* Bb = buf ? Bs1 : Bs0;
#pragma unroll
        for (int ks = 0; ks < 16; ks += 8) {
            uint32_t a[4][4], b[4][2];
#pragma unroll
            for (int i = 0; i < 4; i++) {
                int rb = wm * 64 + i * 16 + grp;
                a[i][0] = __float_as_uint(Ab[(ks + qid    ) * 136 + rb]);
                a[i][1] = __float_as_uint(Ab[(ks + qid    ) * 136 + rb + 8]);
                a[i][2] = __float_as_uint(Ab[(ks + qid + 4) * 136 + rb]);
                a[i][3] = __float_as_uint(Ab[(ks + qid + 4) * 136 + rb + 8]);
            }
#pragma unroll
            for (int j = 0; j < 4; j++) {
                int nb = wn * 32 + j * 8 + grp;
                b[j][0] = __float_as_uint(Bb[(ks + qid    ) * 136 + nb]);
                b[j][1] = __float_as_uint(Bb[(ks + qid + 4) * 136 + nb]);
            }
#pragma unroll
            for (int i = 0; i < 4; i++)
#pragma unroll
                for (int j = 0; j < 4; j++) {
                    asm volatile(
                        "mma.sync.aligned.m16n8k8.row.col.f32.tf32.tf32.f32 "
                        "{%0,%1,%2,%3}, {%4,%5,%6,%7}, {%8,%9}, {%0,%1,%2,%3};\n"
                        : "+f"(acc[i][j][0]), "+f"(acc[i][j][1]),
                          "+f"(acc[i][j][2]), "+f"(acc[i][j][3])
                        : "r"(a[i][0]), "r"(a[i][1]), "r"(a[i][2]), "r"(a[i][3]),
                          "r"(b[j][0]), "r"(b[j][1]));
                }
        }
        if (have_next) {
            if (buf) STS_TILE(As0, Bs0)
            else     STS_TILE(As1, Bs1)
        }
        __syncthreads();
    }
#undef LDG_TILE
#undef STS_TILE

    // reduce column sums -> rscale
    {
        float* red = As0;
        const int g  = t >> 5;
        const int cq = (t & 31) * 4;
        red[g * 128 + cq + 0] = colacc[0];
        red[g * 128 + cq + 1] = colacc[1];
        red[g * 128 + cq + 2] = colacc[2];
        red[g * 128 + cq + 3] = colacc[3];
        __syncthreads();
        if (t < 128) {
            float s = 0.f;
#pragma unroll
            for (int gg = 0; gg < 8; gg++) s += red[gg * 128 + t];
            rsc[t] = 1.f / (1e-9f + s);
        }
        __syncthreads();
    }

    float* Cz = C + (long long)z * sC;
#pragma unroll
    for (int i = 0; i < 4; i++) {
        int r0 = m0 + wm * 64 + i * 16 + grp;
        int r1 = r0 + 8;
        float rsa = rsc[r0 - m0];
        float rsb = rsc[r1 - m0];
#pragma unroll
        for (int j = 0; j < 4; j++) {
            int c = n0 + wn * 32 + j * 8 + qid * 2;
            const float* hpz = p2 + (long long)z * sC;
            float2 o0, o1;
            o0.x = cvt1(hpz[(long long)r0 * ldc + c    ] - acc[i][j][0] * rsa);
            o0.y = cvt1(hpz[(long long)r0 * ldc + c + 1] - acc[i][j][1] * rsa);
            o1.x = cvt1(hpz[(long long)r1 * ldc + c    ] - acc[i][j][2] * rsb);
            o1.y = cvt1(hpz[(long long)r1 * ldc + c + 1] - acc[i][j][3] * rsb);
            *(float2*)&Cz[(long long)r0 * ldc + c] = o0;
            *(float2*)&Cz[(long long)r1 * ldc + c] = o1;
        }
    }
}

// ---------------- softmax over last dim; writes tf32-rounded probabilities -------
__global__ void softmax_rows(float* __restrict__ attn)
{
    __shared__ float red[256];
    float* p = attn + (long long)blockIdx.x * NN;
    const int t = threadIdx.x;
    float v[8];
    float mx = -1e30f;
#pragma unroll
    for (int i = 0; i < 8; i++) { v[i] = p[t + i*256]; mx = fmaxf(mx, v[i]); }
    red[t] = mx; __syncthreads();
    for (int s = 128; s > 0; s >>= 1) {
        if (t < s) red[t] = fmaxf(red[t], red[t + s]);
        __syncthreads();
    }
    mx = red[0]; __syncthreads();
    float sum = 0.f;
#pragma unroll
    for (int i = 0; i < 8; i++) { v[i] = __expf(v[i] - mx); sum += v[i]; }
    red[t] = sum; __syncthreads();
    for (int s = 128; s > 0; s >>= 1) {
        if (t < s) red[t] += red[t + s];
        __syncthreads();
    }
    float inv = 1.f / red[0];
#pragma unroll
    for (int i = 0; i < 8; i++) p[t + i*256] = cvt1(v[i] * inv);
}

// ---------------- out[b,c,i] = h[b,i,c] + t[b,i,c]  (transpose via smem) ---------
__global__ void trans_add(const float* __restrict__ h, const float* __restrict__ tt,
                          float* __restrict__ out)
{
    __shared__ float sh[32][33];
    const int b  = blockIdx.z;
    const int i0 = blockIdx.x * 32, c0 = blockIdx.y * 32;
    const int tx = threadIdx.x, ty = threadIdx.y;   // 32 x 8
#pragma unroll
    for (int r = 0; r < 4; r++) {
        int i = i0 + ty + r * 8;
        long long idx = ((long long)b * NN + i) * CC + c0 + tx;
        sh[ty + r * 8][tx] = h[idx] + tt[idx];
    }
    __syncthreads();
#pragma unroll
    for (int r = 0; r < 4; r++) {
        int c = c0 + ty + r * 8;
        out[((long long)b * CC + c) * NN + i0 + tx] = sh[tx][ty + r * 8];
    }
}

// ==================================================================================
extern "C" void kernel_launch(void* const* d_in, const int* in_sizes, int n_in,
                              void* d_out, int out_size)
{
    const float* x   = (const float*)d_in[0];
    const float* w1  = (const float*)d_in[1];
    const float* w2  = (const float*)d_in[2];
    const float* wqk = (const float*)d_in[3];
    const float* wv  = (const float*)d_in[4];
    const float* bv  = (const float*)d_in[5];
    const float* wt  = (const float*)d_in[6];
    const float* bt  = (const float*)d_in[7];
    const float* bn1g = (const float*)d_in[8],  *bn1b = (const float*)d_in[9];
    const float* bn1m = (const float*)d_in[10], *bn1v = (const float*)d_in[11];
    const float* bn2g = (const float*)d_in[12], *bn2b = (const float*)d_in[13];
    const float* bn2m = (const float*)d_in[14], *bn2v = (const float*)d_in[15];
    const float* bn3g = (const float*)d_in[16], *bn3b = (const float*)d_in[17];
    const float* bn3m = (const float*)d_in[18], *bn3v = (const float*)d_in[19];

    float *h, *q, *v, *u, *attn, *xr, *wr, *bns, *bnh;
    cudaGetSymbolAddress((void**)&h, g_h);
    cudaGetSymbolAddress((void**)&q, g_q);
    cudaGetSymbolAddress((void**)&v, g_v);
    cudaGetSymbolAddress((void**)&u, g_u);
    cudaGetSymbolAddress((void**)&attn, g_attn);
    cudaGetSymbolAddress((void**)&xr, g_xr);
    cudaGetSymbolAddress((void**)&wr, g_wr);
    cudaGetSymbolAddress((void**)&bns, g_bnscale);
    cudaGetSymbolAddress((void**)&bnh, g_bnshift);

    float* w1r  = wr;
    float* w2r  = wr + CC*CC;
    float* wqkr = wr + 2*CC*CC;
    float* wvr  = wr + 3*CC*CC;
    float* wtr  = wr + 4*CC*CC;

    cudaFuncSetAttribute(gemm_ca<1>, cudaFuncAttributeMaxDynamicSharedMemorySize, SMEMCA);
    cudaFuncSetAttribute(gemm_ca<2>, cudaFuncAttributeMaxDynamicSharedMemorySize, SMEMCA);
    cudaFuncSetAttribute(gemm_ca<3>, cudaFuncAttributeMaxDynamicSharedMemorySize, SMEMCA);
    cudaFuncSetAttribute(gemm_ca<5>, cudaFuncAttributeMaxDynamicSharedMemorySize, SMEMCA);
    cudaFuncSetAttribute(gemm_ca<7>, cudaFuncAttributeMaxDynamicSharedMemorySize, SMEMCA);

    bn_prep<<<1, 256>>>(bn1g, bn1b, bn1m, bn1v,
                        bn2g, bn2b, bn2m, bn2v,
                        bn3g, bn3b, bn3m, bn3v, bt);

    // pre-round inputs to tf32 grid
    round_arr<<<(MTOT*CIN/4 + 255)/256, 256>>>(xr, x, MTOT*CIN);
    round_arr<<<(CC*CIN/4 + 255)/256, 256>>>(w1r, w1, CC*CIN);
    round_arr<<<(CC*CC/4 + 255)/256, 256>>>(w2r, w2, CC*CC);
    round_arr<<<(CC*CC/4 + 255)/256, 256>>>(wqkr, wqk, CC*CC);
    round_arr<<<(CC*CC/4 + 255)/256, 256>>>(wvr, wv, CC*CC);
    round_arr<<<(CC*CC/4 + 255)/256, 256>>>(wtr, wt, CC*CC);

    // h1 = cvt(relu(bn1(x @ w1^T)))   (into q as temp)
    gemm_ca<1><<<dim3(CC/128, MTOT/128, 1), 256, SMEMCA>>>(
        xr, w1r, q, CIN, CIN, CIN, CC, 0, 0, 0, bns, bnh);

    // h = cvt(relu(bn2(h1 @ w2^T)))
    gemm_ca<1><<<dim3(CC/128, MTOT/128, 1), 256, SMEMCA>>>(
        q, w2r, h, CC, CC, CC, CC, 0, 0, 0, bns + 256, bnh + 256);

    // q = cvt(h @ wqk^T)
    gemm_ca<3><<<dim3(CC/128, MTOT/128, 1), 256, SMEMCA>>>(
        h, wqkr, q, CC, CC, CC, CC, 0, 0, 0, nullptr, nullptr);

    // v = cvt(h @ wv^T + bv)
    gemm_ca<2><<<dim3(CC/128, MTOT/128, 1), 256, SMEMCA>>>(
        h, wvr, v, CC, CC, CC, CC, 0, 0, 0, bv, nullptr);

    // energy[b,i,j] = q.q  (symmetric, upper-tri pairs, raw store)
    gemm_ca<5><<<dim3(NPAIRS, 1, BB), 256, SMEMCA>>>(
        q, q, attn, CC, CC, CC, NN,
        (long long)NN*CC, (long long)NN*CC, (long long)NN*NN,
        nullptr, nullptr);

    // row softmax (writes tf32-rounded probabilities)
    softmax_rows<<<MTOT, 256>>>(attn);

    // u = cvt(h - attn^T @ v * rscale)   (colsum fused in-CTA)
    gemm_xr<<<dim3(CC/128, NN/128, BB), 256, SMEMB>>>(
        attn, v, u, NN, NN, CC, CC,
        (long long)NN*NN, (long long)NN*CC, (long long)NN*CC, h);

    // t = relu(bn3(u @ wt^T + bt))   (raw store into q)
    gemm_ca<7><<<dim3(CC/128, MTOT/128, 1), 256, SMEMCA>>>(
        u, wtr, q, CC, CC, CC, CC, 0, 0, 0, bns + 512, bnh + 512);

    // out[b,c,i] = h + t, transposed
    trans_add<<<dim3(NN/32, CC/32, BB), dim3(32, 8)>>>(h, q, (float*)d_out);
}

// round 10
// speedup vs baseline: 1.1076x; 1.0278x over previous
#include <cuda_runtime.h>
#include <math.h>
#include <stdint.h>

// Problem constants
#define BB   16
#define NN   2048
#define CIN  64
#define CC   256
#define MTOT (BB*NN)   // 32768
#define NBLK 16        // NN/128
#define NPAIRS 136     // NBLK*(NBLK+1)/2

// cp.async GEMM smem: 4 stages x (2560 A + 2560 B)
#define SMEMCA (8 * 2560 * 4)
// cp.async x_r GEMM smem: 4 stages x (2176 A + 2176 B) + 128 rsc
#define SMEMXR ((8 * 2176 + 128) * 4)

// ---------------- scratch (device globals; no allocation allowed) ----------------
__device__ float g_h[MTOT*CC];
__device__ float g_q[MTOT*CC];
__device__ float g_v[MTOT*CC];
__device__ float g_u[MTOT*CC];
__device__ float g_attn[(size_t)BB*NN*NN];   // 256 MiB
__device__ float g_xr[MTOT*CIN];             // rounded x
__device__ float g_wr[5*CC*CC];              // rounded w1,w2,wqk,wv,wt
__device__ float g_bnscale[3*CC];
__device__ float g_bnshift[3*CC];

// ---------------- BN precompute ----------------
__global__ void bn_prep(const float* __restrict__ g1, const float* __restrict__ b1,
                        const float* __restrict__ m1, const float* __restrict__ v1,
                        const float* __restrict__ g2, const float* __restrict__ b2,
                        const float* __restrict__ m2, const float* __restrict__ v2,
                        const float* __restrict__ g3, const float* __restrict__ b3,
                        const float* __restrict__ m3, const float* __restrict__ v3,
                        const float* __restrict__ bt)
{
    int c = threadIdx.x;
    float s;
    s = g1[c] * rsqrtf(v1[c] + 1e-5f);
    g_bnscale[c]       = s; g_bnshift[c]       = b1[c] - m1[c]*s;
    s = g2[c] * rsqrtf(v2[c] + 1e-5f);
    g_bnscale[256 + c] = s; g_bnshift[256 + c] = b2[c] - m2[c]*s;
    s = g3[c] * rsqrtf(v3[c] + 1e-5f);
    g_bnscale[512 + c] = s; g_bnshift[512 + c] = (bt[c] - m3[c])*s + b3[c];
}

__device__ __forceinline__ uint32_t cvt_tf32(float x) {
    uint32_t u;
    asm("cvt.rna.tf32.f32 %0, %1;" : "=r"(u) : "f"(x));
    return u;
}
__device__ __forceinline__ float cvt1(float x) { return __uint_as_float(cvt_tf32(x)); }

__device__ __forceinline__ float4 cvt4(float4 v) {
    float4 o;
    o.x = cvt1(v.x); o.y = cvt1(v.y); o.z = cvt1(v.z); o.w = cvt1(v.w);
    return o;
}

__device__ __forceinline__ uint32_t smem_u32(const void* p) {
    return (uint32_t)__cvta_generic_to_shared(p);
}
__device__ __forceinline__ void cp_async16(uint32_t dst, const void* src) {
    asm volatile("cp.async.cg.shared.global [%0], [%1], 16;\n" :: "r"(dst), "l"(src));
}

// ---------------- elementwise tf32 pre-round ----------------
__global__ void round_arr(float* __restrict__ dst, const float* __restrict__ src, int n)
{
    int i = (blockIdx.x * 256 + threadIdx.x) * 4;
    if (i < n) *(float4*)&dst[i] = cvt4(*(const float4*)&src[i]);
}

// ================= cp.async 4-stage GEMM (operands pre-rounded tf32) =============
// C[m,n] = sum_k A[m*lda+k] * B[n*ldb+k]   (both operands K-last)
// BM=BN=128, BK=16; 256 threads = 8 warps, warp 64x32 = 4x4 m16n8k8.
// EPI: 1 cvt(relu(acc*p0[c]+p1[c]));  2 cvt(acc+p0[c]);  3 cvt(acc);
//      7 relu(acc*p0[c]+p1[c]) raw;   5 raw symmetric (pair-indexed + mirror)
template<int EPI>
__global__ __launch_bounds__(256, 2)
void gemm_ca(const float* __restrict__ A, const float* __restrict__ B,
             float* __restrict__ C, int K,
             int lda, int ldb, int ldc,
             long long sA, long long sB, long long sC,
             const float* __restrict__ p0, const float* __restrict__ p1)
{
    extern __shared__ float smem[];   // As: [s*2560], Bs: [10240 + s*2560]

    const int z = blockIdx.z;
    A += (long long)z * sA;
    B += (long long)z * sB;

    const int t    = threadIdx.x;
    const int lane = t & 31;
    const int wid  = t >> 5;
    const int wm   = wid >> 2;
    const int wn   = wid & 3;
    const int grp  = lane >> 2;
    const int qid  = lane & 3;

    int m0, n0;
    if (EPI == 5) {
        int rem = blockIdx.x, bi = 0;
        while (rem >= NBLK - bi) { rem -= NBLK - bi; bi++; }
        m0 = bi * 128;
        n0 = (bi + rem) * 128;
    } else {
        m0 = blockIdx.y * 128;
        n0 = blockIdx.x * 128;
    }

    const int row = t >> 2, kq = t & 3;
    const float* aSrc0 = A + (long long)(m0 + row) * lda + kq * 4;
    const float* aSrc1 = aSrc0 + (long long)64 * lda;
    const float* bSrc0 = B + (long long)(n0 + row) * ldb + kq * 4;
    const float* bSrc1 = bSrc0 + (long long)64 * ldb;
    const int off0 = row * 20 + kq * 4;
    const int off1 = off0 + 64 * 20;

#define ISSUE(kit)                                                            \
    {                                                                         \
        int s_ = (kit) & 3;                                                   \
        float* As_ = smem + s_ * 2560;                                        \
        float* Bs_ = smem + 10240 + s_ * 2560;                                \
        long long ko_ = (long long)(kit) * 16;                                \
        cp_async16(smem_u32(As_ + off0), aSrc0 + ko_);                        \
        cp_async16(smem_u32(As_ + off1), aSrc1 + ko_);                        \
        cp_async16(smem_u32(Bs_ + off0), bSrc0 + ko_);                        \
        cp_async16(smem_u32(Bs_ + off1), bSrc1 + ko_);                        \
        asm volatile("cp.async.commit_group;\n");                             \
    }

    float acc[4][4][4];
#pragma unroll
    for (int i = 0; i < 4; i++)
#pragma unroll
        for (int j = 0; j < 4; j++)
#pragma unroll
            for (int e = 0; e < 4; e++) acc[i][j][e] = 0.f;

    const int kIters = K / 16;
    if (0 < kIters) ISSUE(0)
    if (1 < kIters) ISSUE(1)
    if (2 < kIters) ISSUE(2)

    for (int kit = 0; kit < kIters; kit++) {
        int rem = kIters - 1 - kit;
        if (rem >= 2)      asm volatile("cp.async.wait_group 2;\n");
        else if (rem == 1) asm volatile("cp.async.wait_group 1;\n");
        else               asm volatile("cp.async.wait_group 0;\n");
        __syncthreads();
        if (kit + 3 < kIters) ISSUE(kit + 3)

        const float* Ab = smem + (kit & 3) * 2560;
        const float* Bb = smem + 10240 + (kit & 3) * 2560;
#pragma unroll
        for (int ks = 0; ks < 16; ks += 8) {
            uint32_t a[4][4], b[4][2];
#pragma unroll
            for (int i = 0; i < 4; i++) {
                int rb = wm * 64 + i * 16 + grp;
                a[i][0] = __float_as_uint(Ab[(rb    ) * 20 + ks + qid]);
                a[i][1] = __float_as_uint(Ab[(rb + 8) * 20 + ks + qid]);
                a[i][2] = __float_as_uint(Ab[(rb    ) * 20 + ks + 4 + qid]);
                a[i][3] = __float_as_uint(Ab[(rb + 8) * 20 + ks + 4 + qid]);
            }
#pragma unroll
            for (int j = 0; j < 4; j++) {
                int nb = wn * 32 + j * 8 + grp;
                b[j][0] = __float_as_uint(Bb[nb * 20 + ks + qid]);
                b[j][1] = __float_as_uint(Bb[nb * 20 + ks + 4 + qid]);
            }
#pragma unroll
            for (int i = 0; i < 4; i++)
#pragma unroll
                for (int j = 0; j < 4; j++) {
                    asm volatile(
                        "mma.sync.aligned.m16n8k8.row.col.f32.tf32.tf32.f32 "
                        "{%0,%1,%2,%3}, {%4,%5,%6,%7}, {%8,%9}, {%0,%1,%2,%3};\n"
                        : "+f"(acc[i][j][0]), "+f"(acc[i][j][1]),
                          "+f"(acc[i][j][2]), "+f"(acc[i][j][3])
                        : "r"(a[i][0]), "r"(a[i][1]), "r"(a[i][2]), "r"(a[i][3]),
                          "r"(b[j][0]), "r"(b[j][1]));
                }
        }
    }
#undef ISSUE
    __syncthreads();

    // ---- epilogue ----
    float* Cz = C + (long long)z * sC;
#pragma unroll
    for (int i = 0; i < 4; i++) {
        int r0 = m0 + wm * 64 + i * 16 + grp;
        int r1 = r0 + 8;
#pragma unroll
        for (int j = 0; j < 4; j++) {
            int c = n0 + wn * 32 + j * 8 + qid * 2;
            float d0 = acc[i][j][0], d1 = acc[i][j][1];
            float d2 = acc[i][j][2], d3 = acc[i][j][3];
            float2 o0, o1;
            if (EPI == 5) {
                o0 = make_float2(d0, d1);
                o1 = make_float2(d2, d3);
            } else if (EPI == 3) {
                o0 = make_float2(cvt1(d0), cvt1(d1));
                o1 = make_float2(cvt1(d2), cvt1(d3));
            } else if (EPI == 1 || EPI == 7) {
                float s0 = p0[c], s1 = p0[c+1], h0 = p1[c], h1 = p1[c+1];
                o0.x = fmaxf(d0 * s0 + h0, 0.f);
                o0.y = fmaxf(d1 * s1 + h1, 0.f);
                o1.x = fmaxf(d2 * s0 + h0, 0.f);
                o1.y = fmaxf(d3 * s1 + h1, 0.f);
                if (EPI == 1) {
                    o0.x = cvt1(o0.x); o0.y = cvt1(o0.y);
                    o1.x = cvt1(o1.x); o1.y = cvt1(o1.y);
                }
            } else { // EPI == 2
                float h0 = p0[c], h1 = p0[c+1];
                o0 = make_float2(cvt1(d0 + h0), cvt1(d1 + h1));
                o1 = make_float2(cvt1(d2 + h0), cvt1(d3 + h1));
            }
            *(float2*)&Cz[(long long)r0 * ldc + c] = o0;
            *(float2*)&Cz[(long long)r1 * ldc + c] = o1;
        }
    }

    // ---- EPI5 off-diagonal: mirrored (transposed) store via smem staging ----
    if (EPI == 5 && m0 != n0) {
        float* sm_t = smem;   // 64 x 132 floats
#pragma unroll
        for (int half = 0; half < 2; half++) {
            __syncthreads();
            if (wm == half) {
#pragma unroll
                for (int i = 0; i < 4; i++) {
                    int rl = i * 16 + grp;
#pragma unroll
                    for (int j = 0; j < 4; j++) {
                        int c = wn * 32 + j * 8 + qid * 2;
                        sm_t[rl * 132 + c]           = acc[i][j][0];
                        sm_t[rl * 132 + c + 1]       = acc[i][j][1];
                        sm_t[(rl + 8) * 132 + c]     = acc[i][j][2];
                        sm_t[(rl + 8) * 132 + c + 1] = acc[i][j][3];
                    }
                }
            }
            __syncthreads();
            int c   = t >> 1;
            int seg = (t & 1) * 32;
            float* dst = Cz + (long long)(n0 + c) * ldc + m0 + half * 64 + seg;
#pragma unroll
            for (int s = 0; s < 32; s += 4) {
                float4 o;
                o.x = sm_t[(seg + s + 0) * 132 + c];
                o.y = sm_t[(seg + s + 1) * 132 + c];
                o.z = sm_t[(seg + s + 2) * 132 + c];
                o.w = sm_t[(seg + s + 3) * 132 + c];
                *(float4*)(dst + s) = o;
            }
        }
    }
}

// ======= cp.async 4-stage GEMM for x_r: attn^T @ v with fused colsum =============
// A trans [k][m] (attn, rounded in gmem), B trans [k][n] (v, rounded in gmem).
// u[r,c] = cvt( h[r,c] - acc * rscale[r] ),  rscale from in-CTA column sums
// (colacc accumulated by reading back this thread's own smem slots post-wait —
//  identical values to register staging since gmem already holds rounded bits).
__global__ __launch_bounds__(256, 2)
void gemm_xr(const float* __restrict__ A, const float* __restrict__ B,
             float* __restrict__ C, int K,
             int lda, int ldb, int ldc,
             long long sA, long long sB, long long sC,
             const float* __restrict__ p2)
{
    extern __shared__ float smem[];   // As: s*2176, Bs: 8704 + s*2176, rsc: 17408
    float* rsc = smem + 8 * 2176;

    const int z = blockIdx.z;
    A += (long long)z * sA;
    B += (long long)z * sB;

    const int t    = threadIdx.x;
    const int lane = t & 31;
    const int wid  = t >> 5;
    const int wm   = wid >> 2;
    const int wn   = wid & 3;
    const int grp  = lane >> 2;
    const int qid  = lane & 3;
    const int m0   = blockIdx.y * 128;
    const int n0   = blockIdx.x * 128;

    // trans staging: thread covers k-rows (t>>5) and (t>>5)+8, 4 cols at (t&31)*4
    const int kk = t >> 5, cq = (t & 31) * 4;
    const long long aStep = (long long)lda * 16;
    const long long bStep = (long long)ldb * 16;
    const float* aP0 = A + (long long)kk * lda + m0 + cq;
    const float* aP1 = A + (long long)(kk + 8) * lda + m0 + cq;
    const float* bP0 = B + (long long)kk * ldb + n0 + cq;
    const float* bP1 = B + (long long)(kk + 8) * ldb + n0 + cq;
    const int aS0 = kk * 136 + cq;
    const int aS1 = aS0 + 8 * 136;

#define ISSUEX(kit)                                                           \
    {                                                                         \
        int s_ = (kit) & 3;                                                   \
        float* As_ = smem + s_ * 2176;                                        \
        float* Bs_ = smem + 8704 + s_ * 2176;                                 \
        long long ko_ = (long long)(kit) * aStep;                             \
        long long kb_ = (long long)(kit) * bStep;                             \
        cp_async16(smem_u32(As_ + aS0), aP0 + ko_);                           \
        cp_async16(smem_u32(As_ + aS1), aP1 + ko_);                           \
        cp_async16(smem_u32(Bs_ + aS0), bP0 + kb_);                           \
        cp_async16(smem_u32(Bs_ + aS1), bP1 + kb_);                           \
        asm volatile("cp.async.commit_group;\n");                             \
    }

    float acc[4][4][4];
#pragma unroll
    for (int i = 0; i < 4; i++)
#pragma unroll
        for (int j = 0; j < 4; j++)
#pragma unroll
            for (int e = 0; e < 4; e++) acc[i][j][e] = 0.f;

    float colacc[4] = {0.f, 0.f, 0.f, 0.f};

    const int kIters = K / 16;
    ISSUEX(0)
    ISSUEX(1)
    ISSUEX(2)

    for (int kit = 0; kit < kIters; kit++) {
        int rem = kIters - 1 - kit;
        if (rem >= 2)      asm volatile("cp.async.wait_group 2;\n");
        else if (rem == 1) asm volatile("cp.async.wait_group 1;\n");
        else               asm volatile("cp.async.wait_group 0;\n");
        __syncthreads();
        if (kit + 3 < kIters) ISSUEX(kit + 3)

        const float* Ab = smem + (kit & 3) * 2176;
        const float* Bb = smem + 8704 + (kit & 3) * 2176;

        // fused column-sum: read back this thread's own staged attn elements
        {
            float4 ca0 = *(const float4*)&Ab[aS0];
            float4 ca1 = *(const float4*)&Ab[aS1];
            colacc[0] += ca0.x + ca1.x;
            colacc[1] += ca0.y + ca1.y;
            colacc[2] += ca0.z + ca1.z;
            colacc[3] += ca0.w + ca1.w;
        }

#pragma unroll
        for (int ks = 0; ks < 16; ks += 8) {
            uint32_t a[4][4], b[4][2];
#pragma unroll
            for (int i = 0; i < 4; i++) {
                int rb = wm * 64 + i * 16 + grp;
                a[i][0] = __float_as_uint(Ab[(ks + qid    ) * 136 + rb]);
                a[i][1] = __float_as_uint(Ab[(ks + qid    ) * 136 + rb + 8]);
                a[i][2] = __float_as_uint(Ab[(ks + qid + 4) * 136 + rb]);
                a[i][3] = __float_as_uint(Ab[(ks + qid + 4) * 136 + rb + 8]);
            }
#pragma unroll
            for (int j = 0; j < 4; j++) {
                int nb = wn * 32 + j * 8 + grp;
                b[j][0] = __float_as_uint(Bb[(ks + qid    ) * 136 + nb]);
                b[j][1] = __float_as_uint(Bb[(ks + qid + 4) * 136 + nb]);
            }
#pragma unroll
            for (int i = 0; i < 4; i++)
#pragma unroll
                for (int j = 0; j < 4; j++) {
                    asm volatile(
                        "mma.sync.aligned.m16n8k8.row.col.f32.tf32.tf32.f32 "
                        "{%0,%1,%2,%3}, {%4,%5,%6,%7}, {%8,%9}, {%0,%1,%2,%3};\n"
                        : "+f"(acc[i][j][0]), "+f"(acc[i][j][1]),
                          "+f"(acc[i][j][2]), "+f"(acc[i][j][3])
                        : "r"(a[i][0]), "r"(a[i][1]), "r"(a[i][2]), "r"(a[i][3]),
                          "r"(b[j][0]), "r"(b[j][1]));
                }
        }
    }
#undef ISSUEX
    __syncthreads();

    // reduce column sums -> rscale (thread t covered columns cq..cq+3, k-rows kk,kk+8)
    {
        float* red = smem;   // 8 groups x 128 columns
        red[kk * 128 + cq + 0] = colacc[0];
        red[kk * 128 + cq + 1] = colacc[1];
        red[kk * 128 + cq + 2] = colacc[2];
        red[kk * 128 + cq + 3] = colacc[3];
        __syncthreads();
        if (t < 128) {
            float s = 0.f;
#pragma unroll
            for (int gg = 0; gg < 8; gg++) s += red[gg * 128 + t];
            rsc[t] = 1.f / (1e-9f + s);
        }
        __syncthreads();
    }

    float* Cz = C + (long long)z * sC;
#pragma unroll
    for (int i = 0; i < 4; i++) {
        int r0 = m0 + wm * 64 + i * 16 + grp;
        int r1 = r0 + 8;
        float rsa = rsc[r0 - m0];
        float rsb = rsc[r1 - m0];
#pragma unroll
        for (int j = 0; j < 4; j++) {
            int c = n0 + wn * 32 + j * 8 + qid * 2;
            const float* hpz = p2 + (long long)z * sC;
            float2 o0, o1;
            o0.x = cvt1(hpz[(long long)r0 * ldc + c    ] - acc[i][j][0] * rsa);
            o0.y = cvt1(hpz[(long long)r0 * ldc + c + 1] - acc[i][j][1] * rsa);
            o1.x = cvt1(hpz[(long long)r1 * ldc + c    ] - acc[i][j][2] * rsb);
            o1.y = cvt1(hpz[(long long)r1 * ldc + c + 1] - acc[i][j][3] * rsb);
            *(float2*)&Cz[(long long)r0 * ldc + c] = o0;
            *(float2*)&Cz[(long long)r1 * ldc + c] = o1;
        }
    }
}

// ---------------- softmax over last dim; writes tf32-rounded probabilities -------
__global__ void softmax_rows(float* __restrict__ attn)
{
    __shared__ float red[256];
    float* p = attn + (long long)blockIdx.x * NN;
    const int t = threadIdx.x;
    float v[8];
    float mx = -1e30f;
#pragma unroll
    for (int i = 0; i < 8; i++) { v[i] = p[t + i*256]; mx = fmaxf(mx, v[i]); }
    red[t] = mx; __syncthreads();
    for (int s = 128; s > 0; s >>= 1) {
        if (t < s) red[t] = fmaxf(red[t], red[t + s]);
        __syncthreads();
    }
    mx = red[0]; __syncthreads();
    float sum = 0.f;
#pragma unroll
    for (int i = 0; i < 8; i++) { v[i] = __expf(v[i] - mx); sum += v[i]; }
    red[t] = sum; __syncthreads();
    for (int s = 128; s > 0; s >>= 1) {
        if (t < s) red[t] += red[t + s];
        __syncthreads();
    }
    float inv = 1.f / red[0];
#pragma unroll
    for (int i = 0; i < 8; i++) p[t + i*256] = cvt1(v[i] * inv);
}

// ---------------- out[b,c,i] = h[b,i,c] + t[b,i,c]  (transpose via smem) ---------
__global__ void trans_add(const float* __restrict__ h, const float* __restrict__ tt,
                          float* __restrict__ out)
{
    __shared__ float sh[32][33];
    const int b  = blockIdx.z;
    const int i0 = blockIdx.x * 32, c0 = blockIdx.y * 32;
    const int tx = threadIdx.x, ty = threadIdx.y;   // 32 x 8
#pragma unroll
    for (int r = 0; r < 4; r++) {
        int i = i0 + ty + r * 8;
        long long idx = ((long long)b * NN + i) * CC + c0 + tx;
        sh[ty + r * 8][tx] = h[idx] + tt[idx];
    }
    __syncthreads();
#pragma unroll
    for (int r = 0; r < 4; r++) {
        int c = c0 + ty + r * 8;
        out[((long long)b * CC + c) * NN + i0 + tx] = sh[tx][ty + r * 8];
    }
}

// ==================================================================================
extern "C" void kernel_launch(void* const* d_in, const int* in_sizes, int n_in,
                              void* d_out, int out_size)
{
    const float* x   = (const float*)d_in[0];
    const float* w1  = (const float*)d_in[1];
    const float* w2  = (const float*)d_in[2];
    const float* wqk = (const float*)d_in[3];
    const float* wv  = (const float*)d_in[4];
    const float* bv  = (const float*)d_in[5];
    const float* wt  = (const float*)d_in[6];
    const float* bt  = (const float*)d_in[7];
    const float* bn1g = (const float*)d_in[8],  *bn1b = (const float*)d_in[9];
    const float* bn1m = (const float*)d_in[10], *bn1v = (const float*)d_in[11];
    const float* bn2g = (const float*)d_in[12], *bn2b = (const float*)d_in[13];
    const float* bn2m = (const float*)d_in[14], *bn2v = (const float*)d_in[15];
    const float* bn3g = (const float*)d_in[16], *bn3b = (const float*)d_in[17];
    const float* bn3m = (const float*)d_in[18], *bn3v = (const float*)d_in[19];

    float *h, *q, *v, *u, *attn, *xr, *wr, *bns, *bnh;
    cudaGetSymbolAddress((void**)&h, g_h);
    cudaGetSymbolAddress((void**)&q, g_q);
    cudaGetSymbolAddress((void**)&v, g_v);
    cudaGetSymbolAddress((void**)&u, g_u);
    cudaGetSymbolAddress((void**)&attn, g_attn);
    cudaGetSymbolAddress((void**)&xr, g_xr);
    cudaGetSymbolAddress((void**)&wr, g_wr);
    cudaGetSymbolAddress((void**)&bns, g_bnscale);
    cudaGetSymbolAddress((void**)&bnh, g_bnshift);

    float* w1r  = wr;
    float* w2r  = wr + CC*CC;
    float* wqkr = wr + 2*CC*CC;
    float* wvr  = wr + 3*CC*CC;
    float* wtr  = wr + 4*CC*CC;

    cudaFuncSetAttribute(gemm_ca<1>, cudaFuncAttributeMaxDynamicSharedMemorySize, SMEMCA);
    cudaFuncSetAttribute(gemm_ca<2>, cudaFuncAttributeMaxDynamicSharedMemorySize, SMEMCA);
    cudaFuncSetAttribute(gemm_ca<3>, cudaFuncAttributeMaxDynamicSharedMemorySize, SMEMCA);
    cudaFuncSetAttribute(gemm_ca<5>, cudaFuncAttributeMaxDynamicSharedMemorySize, SMEMCA);
    cudaFuncSetAttribute(gemm_ca<7>, cudaFuncAttributeMaxDynamicSharedMemorySize, SMEMCA);
    cudaFuncSetAttribute(gemm_xr,    cudaFuncAttributeMaxDynamicSharedMemorySize, SMEMXR);

    bn_prep<<<1, 256>>>(bn1g, bn1b, bn1m, bn1v,
                        bn2g, bn2b, bn2m, bn2v,
                        bn3g, bn3b, bn3m, bn3v, bt);

    // pre-round inputs to tf32 grid
    round_arr<<<(MTOT*CIN/4 + 255)/256, 256>>>(xr, x, MTOT*CIN);
    round_arr<<<(CC*CIN/4 + 255)/256, 256>>>(w1r, w1, CC*CIN);
    round_arr<<<(CC*CC/4 + 255)/256, 256>>>(w2r, w2, CC*CC);
    round_arr<<<(CC*CC/4 + 255)/256, 256>>>(wqkr, wqk, CC*CC);
    round_arr<<<(CC*CC/4 + 255)/256, 256>>>(wvr, wv, CC*CC);
    round_arr<<<(CC*CC/4 + 255)/256, 256>>>(wtr, wt, CC*CC);

    // h1 = cvt(relu(bn1(x @ w1^T)))   (into q as temp)
    gemm_ca<1><<<dim3(CC/128, MTOT/128, 1), 256, SMEMCA>>>(
        xr, w1r, q, CIN, CIN, CIN, CC, 0, 0, 0, bns, bnh);

    // h = cvt(relu(bn2(h1 @ w2^T)))
    gemm_ca<1><<<dim3(CC/128, MTOT/128, 1), 256, SMEMCA>>>(
        q, w2r, h, CC, CC, CC, CC, 0, 0, 0, bns + 256, bnh + 256);

    // q = cvt(h @ wqk^T)
    gemm_ca<3><<<dim3(CC/128, MTOT/128, 1), 256, SMEMCA>>>(
        h, wqkr, q, CC, CC, CC, CC, 0, 0, 0, nullptr, nullptr);

    // v = cvt(h @ wv^T + bv)
    gemm_ca<2><<<dim3(CC/128, MTOT/128, 1), 256, SMEMCA>>>(
        h, wvr, v, CC, CC, CC, CC, 0, 0, 0, bv, nullptr);

    // energy[b,i,j] = q.q  (symmetric, upper-tri pairs, raw store)
    gemm_ca<5><<<dim3(NPAIRS, 1, BB), 256, SMEMCA>>>(
        q, q, attn, CC, CC, CC, NN,
        (long long)NN*CC, (long long)NN*CC, (long long)NN*NN,
        nullptr, nullptr);

    // row softmax (writes tf32-rounded probabilities)
    softmax_rows<<<MTOT, 256>>>(attn);

    // u = cvt(h - attn^T @ v * rscale)   (colsum fused in-CTA; cp.async pipeline)
    gemm_xr<<<dim3(CC/128, NN/128, BB), 256, SMEMXR>>>(
        attn, v, u, NN, NN, CC, CC,
        (long long)NN*NN, (long long)NN*CC, (long long)NN*CC, h);

    // t = relu(bn3(u @ wt^T + bt))   (raw store into q)
    gemm_ca<7><<<dim3(CC/128, MTOT/128, 1), 256, SMEMCA>>>(
        u, wtr, q, CC, CC, CC, CC, 0, 0, 0, bns + 512, bnh + 512);

    // out[b,c,i] = h + t, transposed
    trans_add<<<dim3(NN/32, CC/32, BB), dim3(32, 8)>>>(h, q, (float*)d_out);
}

// round 11
// speedup vs baseline: 1.1123x; 1.0042x over previous
#include <cuda_runtime.h>
#include <math.h>
#include <stdint.h>

// Problem constants
#define BB   16
#define NN   2048
#define CIN  64
#define CC   256
#define MTOT (BB*NN)   // 32768
#define NBLK 16        // NN/128
#define NPAIRS 136     // NBLK*(NBLK+1)/2

// cp.async GEMM smem: 4 stages x (2560 A + 2560 B)
#define SMEMCA (8 * 2560 * 4)
// cp.async x_r GEMM smem: 4 stages x (2176 A + 2176 B) + 128 rsc
#define SMEMXR ((8 * 2176 + 128) * 4)

// ---------------- scratch (device globals; no allocation allowed) ----------------
__device__ float g_h[MTOT*CC];
__device__ float g_q[MTOT*CC];
__device__ float g_v[MTOT*CC];
__device__ float g_u[MTOT*CC];
__device__ float g_attn[(size_t)BB*NN*NN];   // 256 MiB
__device__ float g_xr[MTOT*CIN];             // rounded x
__device__ float g_wr[5*CC*CC];              // rounded w1,w2,wqk,wv,wt
__device__ float g_bnscale[3*CC];
__device__ float g_bnshift[3*CC];

// ---------------- BN precompute ----------------
__global__ void bn_prep(const float* __restrict__ g1, const float* __restrict__ b1,
                        const float* __restrict__ m1, const float* __restrict__ v1,
                        const float* __restrict__ g2, const float* __restrict__ b2,
                        const float* __restrict__ m2, const float* __restrict__ v2,
                        const float* __restrict__ g3, const float* __restrict__ b3,
                        const float* __restrict__ m3, const float* __restrict__ v3,
                        const float* __restrict__ bt)
{
    int c = threadIdx.x;
    float s;
    s = g1[c] * rsqrtf(v1[c] + 1e-5f);
    g_bnscale[c]       = s; g_bnshift[c]       = b1[c] - m1[c]*s;
    s = g2[c] * rsqrtf(v2[c] + 1e-5f);
    g_bnscale[256 + c] = s; g_bnshift[256 + c] = b2[c] - m2[c]*s;
    s = g3[c] * rsqrtf(v3[c] + 1e-5f);
    g_bnscale[512 + c] = s; g_bnshift[512 + c] = (bt[c] - m3[c])*s + b3[c];
}

__device__ __forceinline__ uint32_t cvt_tf32(float x) {
    uint32_t u;
    asm("cvt.rna.tf32.f32 %0, %1;" : "=r"(u) : "f"(x));
    return u;
}
__device__ __forceinline__ float cvt1(float x) { return __uint_as_float(cvt_tf32(x)); }

__device__ __forceinline__ float4 cvt4(float4 v) {
    float4 o;
    o.x = cvt1(v.x); o.y = cvt1(v.y); o.z = cvt1(v.z); o.w = cvt1(v.w);
    return o;
}

__device__ __forceinline__ uint32_t smem_u32(const void* p) {
    return (uint32_t)__cvta_generic_to_shared(p);
}
__device__ __forceinline__ void cp_async16(uint32_t dst, const void* src) {
    asm volatile("cp.async.cg.shared.global [%0], [%1], 16;\n" :: "r"(dst), "l"(src));
}

// ---------------- elementwise tf32 pre-round: x (big array) ----------------
__global__ void round_x(float* __restrict__ dst, const float* __restrict__ src, int n)
{
    int i = (blockIdx.x * 256 + threadIdx.x) * 4;
    if (i < n) *(float4*)&dst[i] = cvt4(*(const float4*)&src[i]);
}

// ---------------- elementwise tf32 pre-round: all 5 weights in one launch -------
__global__ void round_w(float* __restrict__ dst,
                        const float* __restrict__ s0, const float* __restrict__ s1,
                        const float* __restrict__ s2, const float* __restrict__ s3,
                        const float* __restrict__ s4)
{
    const float* srcs[5] = {s0, s1, s2, s3, s4};
    const int ns[5] = {CC*CIN, CC*CC, CC*CC, CC*CC, CC*CC};
    const int offs[5] = {0, CC*CC, 2*CC*CC, 3*CC*CC, 4*CC*CC};
    int tid = blockIdx.x * 256 + threadIdx.x;
    int stride = gridDim.x * 256;
#pragma unroll
    for (int a = 0; a < 5; a++) {
        const float* s = srcs[a];
        float* d = dst + offs[a];
        for (int i = tid * 4; i < ns[a]; i += stride * 4)
            *(float4*)&d[i] = cvt4(*(const float4*)&s[i]);
    }
}

// ================= cp.async 4-stage GEMM (operands pre-rounded tf32) =============
// C[m,n] = sum_k A[m*lda+k] * B[n*ldb+k]   (both operands K-last)
// BM=BN=128, BK=16; 256 threads = 8 warps, warp 64x32 = 4x4 m16n8k8.
// EPI: 1 cvt(relu(acc*p0[c]+p1[c]));  2 cvt(acc+p0[c]);  3 cvt(acc);
//      5 raw symmetric (pair-indexed + mirror);
//      6 fused final: out[b,c,i] = p2[r,c] + relu(acc*p0[c]+p1[c]),
//        stored TRANSPOSED ([B,C,N]) via smem staging.
template<int EPI>
__global__ __launch_bounds__(256, 2)
void gemm_ca(const float* __restrict__ A, const float* __restrict__ B,
             float* __restrict__ C, int K,
             int lda, int ldb, int ldc,
             long long sA, long long sB, long long sC,
             const float* __restrict__ p0, const float* __restrict__ p1,
             const float* __restrict__ p2)
{
    extern __shared__ float smem[];   // As: [s*2560], Bs: [10240 + s*2560]

    const int z = blockIdx.z;
    A += (long long)z * sA;
    B += (long long)z * sB;

    const int t    = threadIdx.x;
    const int lane = t & 31;
    const int wid  = t >> 5;
    const int wm   = wid >> 2;
    const int wn   = wid & 3;
    const int grp  = lane >> 2;
    const int qid  = lane & 3;

    int m0, n0;
    if (EPI == 5) {
        int rem = blockIdx.x, bi = 0;
        while (rem >= NBLK - bi) { rem -= NBLK - bi; bi++; }
        m0 = bi * 128;
        n0 = (bi + rem) * 128;
    } else {
        m0 = blockIdx.y * 128;
        n0 = blockIdx.x * 128;
    }

    const int row = t >> 2, kq = t & 3;
    const float* aSrc0 = A + (long long)(m0 + row) * lda + kq * 4;
    const float* aSrc1 = aSrc0 + (long long)64 * lda;
    const float* bSrc0 = B + (long long)(n0 + row) * ldb + kq * 4;
    const float* bSrc1 = bSrc0 + (long long)64 * ldb;
    const int off0 = row * 20 + kq * 4;
    const int off1 = off0 + 64 * 20;

#define ISSUE(kit)                                                            \
    {                                                                         \
        int s_ = (kit) & 3;                                                   \
        float* As_ = smem + s_ * 2560;                                        \
        float* Bs_ = smem + 10240 + s_ * 2560;                                \
        long long ko_ = (long long)(kit) * 16;                                \
        cp_async16(smem_u32(As_ + off0), aSrc0 + ko_);                        \
        cp_async16(smem_u32(As_ + off1), aSrc1 + ko_);                        \
        cp_async16(smem_u32(Bs_ + off0), bSrc0 + ko_);                        \
        cp_async16(smem_u32(Bs_ + off1), bSrc1 + ko_);                        \
        asm volatile("cp.async.commit_group;\n");                             \
    }

    float acc[4][4][4];
#pragma unroll
    for (int i = 0; i < 4; i++)
#pragma unroll
        for (int j = 0; j < 4; j++)
#pragma unroll
            for (int e = 0; e < 4; e++) acc[i][j][e] = 0.f;

    const int kIters = K / 16;
    if (0 < kIters) ISSUE(0)
    if (1 < kIters) ISSUE(1)
    if (2 < kIters) ISSUE(2)

    for (int kit = 0; kit < kIters; kit++) {
        int rem = kIters - 1 - kit;
        if (rem >= 2)      asm volatile("cp.async.wait_group 2;\n");
        else if (rem == 1) asm volatile("cp.async.wait_group 1;\n");
        else               asm volatile("cp.async.wait_group 0;\n");
        __syncthreads();
        if (kit + 3 < kIters) ISSUE(kit + 3)

        const float* Ab = smem + (kit & 3) * 2560;
        const float* Bb = smem + 10240 + (kit & 3) * 2560;
#pragma unroll
        for (int ks = 0; ks < 16; ks += 8) {
            uint32_t a[4][4], b[4][2];
#pragma unroll
            for (int i = 0; i < 4; i++) {
                int rb = wm * 64 + i * 16 + grp;
                a[i][0] = __float_as_uint(Ab[(rb    ) * 20 + ks + qid]);
                a[i][1] = __float_as_uint(Ab[(rb + 8) * 20 + ks + qid]);
                a[i][2] = __float_as_uint(Ab[(rb    ) * 20 + ks + 4 + qid]);
                a[i][3] = __float_as_uint(Ab[(rb + 8) * 20 + ks + 4 + qid]);
            }
#pragma unroll
            for (int j = 0; j < 4; j++) {
                int nb = wn * 32 + j * 8 + grp;
                b[j][0] = __float_as_uint(Bb[nb * 20 + ks + qid]);
                b[j][1] = __float_as_uint(Bb[nb * 20 + ks + 4 + qid]);
            }
#pragma unroll
            for (int i = 0; i < 4; i++)
#pragma unroll
                for (int j = 0; j < 4; j++) {
                    asm volatile(
                        "mma.sync.aligned.m16n8k8.row.col.f32.tf32.tf32.f32 "
                        "{%0,%1,%2,%3}, {%4,%5,%6,%7}, {%8,%9}, {%0,%1,%2,%3};\n"
                        : "+f"(acc[i][j][0]), "+f"(acc[i][j][1]),
                          "+f"(acc[i][j][2]), "+f"(acc[i][j][3])
                        : "r"(a[i][0]), "r"(a[i][1]), "r"(a[i][2]), "r"(a[i][3]),
                          "r"(b[j][0]), "r"(b[j][1]));
                }
        }
    }
#undef ISSUE
    __syncthreads();

    float* Cz = C + (long long)z * sC;

    // ---- epilogue: direct store (all EPIs except 6) ----
    if (EPI != 6) {
#pragma unroll
        for (int i = 0; i < 4; i++) {
            int r0 = m0 + wm * 64 + i * 16 + grp;
            int r1 = r0 + 8;
#pragma unroll
            for (int j = 0; j < 4; j++) {
                int c = n0 + wn * 32 + j * 8 + qid * 2;
                float d0 = acc[i][j][0], d1 = acc[i][j][1];
                float d2 = acc[i][j][2], d3 = acc[i][j][3];
                float2 o0, o1;
                if (EPI == 5) {
                    o0 = make_float2(d0, d1);
                    o1 = make_float2(d2, d3);
                } else if (EPI == 3) {
                    o0 = make_float2(cvt1(d0), cvt1(d1));
                    o1 = make_float2(cvt1(d2), cvt1(d3));
                } else if (EPI == 1) {
                    float s0 = p0[c], s1 = p0[c+1], h0 = p1[c], h1 = p1[c+1];
                    o0.x = cvt1(fmaxf(d0 * s0 + h0, 0.f));
                    o0.y = cvt1(fmaxf(d1 * s1 + h1, 0.f));
                    o1.x = cvt1(fmaxf(d2 * s0 + h0, 0.f));
                    o1.y = cvt1(fmaxf(d3 * s1 + h1, 0.f));
                } else { // EPI == 2
                    float h0 = p0[c], h1 = p0[c+1];
                    o0 = make_float2(cvt1(d0 + h0), cvt1(d1 + h1));
                    o1 = make_float2(cvt1(d2 + h0), cvt1(d3 + h1));
                }
                *(float2*)&Cz[(long long)r0 * ldc + c] = o0;
                *(float2*)&Cz[(long long)r1 * ldc + c] = o1;
            }
        }
    }

    // ---- EPI5 off-diagonal: mirrored (transposed) store via smem staging ----
    if (EPI == 5 && m0 != n0) {
        float* sm_t = smem;   // 64 x 132 floats
#pragma unroll
        for (int half = 0; half < 2; half++) {
            __syncthreads();
            if (wm == half) {
#pragma unroll
                for (int i = 0; i < 4; i++) {
                    int rl = i * 16 + grp;
#pragma unroll
                    for (int j = 0; j < 4; j++) {
                        int c = wn * 32 + j * 8 + qid * 2;
                        sm_t[rl * 132 + c]           = acc[i][j][0];
                        sm_t[rl * 132 + c + 1]       = acc[i][j][1];
                        sm_t[(rl + 8) * 132 + c]     = acc[i][j][2];
                        sm_t[(rl + 8) * 132 + c + 1] = acc[i][j][3];
                    }
                }
            }
            __syncthreads();
            int c   = t >> 1;
            int seg = (t & 1) * 32;
            float* dst = Cz + (long long)(n0 + c) * ldc + m0 + half * 64 + seg;
#pragma unroll
            for (int s = 0; s < 32; s += 4) {
                float4 o;
                o.x = sm_t[(seg + s + 0) * 132 + c];
                o.y = sm_t[(seg + s + 1) * 132 + c];
                o.z = sm_t[(seg + s + 2) * 132 + c];
                o.w = sm_t[(seg + s + 3) * 132 + c];
                *(float4*)(dst + s) = o;
            }
        }
    }

    // ---- EPI6: out[b,c,i] = p2[r,c] + relu(acc*p0[c]+p1[c]), transposed store ----
    if (EPI == 6) {
#pragma unroll
        for (int i = 0; i < 4; i++) {
            int r0 = m0 + wm * 64 + i * 16 + grp;
            int r1 = r0 + 8;
#pragma unroll
            for (int j = 0; j < 4; j++) {
                int c = n0 + wn * 32 + j * 8 + qid * 2;
                float s0 = p0[c], s1 = p0[c+1], h0 = p1[c], h1 = p1[c+1];
                acc[i][j][0] = p2[(long long)r0 * ldc + c    ] + fmaxf(acc[i][j][0] * s0 + h0, 0.f);
                acc[i][j][1] = p2[(long long)r0 * ldc + c + 1] + fmaxf(acc[i][j][1] * s1 + h1, 0.f);
                acc[i][j][2] = p2[(long long)r1 * ldc + c    ] + fmaxf(acc[i][j][2] * s0 + h0, 0.f);
                acc[i][j][3] = p2[(long long)r1 * ldc + c + 1] + fmaxf(acc[i][j][3] * s1 + h1, 0.f);
            }
        }
        const int zb = m0 >> 11;          // batch index (m0 / NN)
        const int ib = m0 & (NN - 1);     // token base within batch
        float* outz = C + ((long long)zb * CC + n0) * NN;
        float* sm_t = smem;               // 64 x 132 floats
#pragma unroll
        for (int half = 0; half < 2; half++) {
            __syncthreads();
            if (wm == half) {
#pragma unroll
                for (int i = 0; i < 4; i++) {
                    int rl = i * 16 + grp;
#pragma unroll
                    for (int j = 0; j < 4; j++) {
                        int c = wn * 32 + j * 8 + qid * 2;
                        sm_t[rl * 132 + c]           = acc[i][j][0];
                        sm_t[rl * 132 + c + 1]       = acc[i][j][1];
                        sm_t[(rl + 8) * 132 + c]     = acc[i][j][2];
                        sm_t[(rl + 8) * 132 + c + 1] = acc[i][j][3];
                    }
                }
            }
            __syncthreads();
            // write out[(zb*CC + n0 + c)][ib + half*64 + 0..63], coalesced float4
            int c   = t >> 1;
            int seg = (t & 1) * 32;
            float* dst = outz + (long long)c * NN + ib + half * 64 + seg;
#pragma unroll
            for (int s = 0; s < 32; s += 4) {
                float4 o;
                o.x = sm_t[(seg + s + 0) * 132 + c];
                o.y = sm_t[(seg + s + 1) * 132 + c];
                o.z = sm_t[(seg + s + 2) * 132 + c];
                o.w = sm_t[(seg + s + 3) * 132 + c];
                *(float4*)(dst + s) = o;
            }
        }
    }
}

// ======= cp.async 4-stage GEMM for x_r: attn^T @ v with fused colsum =============
// A trans [k][m] (attn, rounded in gmem), B trans [k][n] (v, rounded in gmem).
// u[r,c] = cvt( h[r,c] - acc * rscale[r] ),  rscale from in-CTA column sums.
__global__ __launch_bounds__(256, 2)
void gemm_xr(const float* __restrict__ A, const float* __restrict__ B,
             float* __restrict__ C, int K,
             int lda, int ldb, int ldc,
             long long sA, long long sB, long long sC,
             const float* __restrict__ p2)
{
    extern __shared__ float smem[];   // As: s*2176, Bs: 8704 + s*2176, rsc: 17408
    float* rsc = smem + 8 * 2176;

    const int z = blockIdx.z;
    A += (long long)z * sA;
    B += (long long)z * sB;

    const int t    = threadIdx.x;
    const int lane = t & 31;
    const int wid  = t >> 5;
    const int wm   = wid >> 2;
    const int wn   = wid & 3;
    const int grp  = lane >> 2;
    const int qid  = lane & 3;
    const int m0   = blockIdx.y * 128;
    const int n0   = blockIdx.x * 128;

    const int kk = t >> 5, cq = (t & 31) * 4;
    const long long aStep = (long long)lda * 16;
    const long long bStep = (long long)ldb * 16;
    const float* aP0 = A + (long long)kk * lda + m0 + cq;
    const float* aP1 = A + (long long)(kk + 8) * lda + m0 + cq;
    const float* bP0 = B + (long long)kk * ldb + n0 + cq;
    const float* bP1 = B + (long long)(kk + 8) * ldb + n0 + cq;
    const int aS0 = kk * 136 + cq;
    const int aS1 = aS0 + 8 * 136;

#define ISSUEX(kit)                                                           \
    {                                                                         \
        int s_ = (kit) & 3;                                                   \
        float* As_ = smem + s_ * 2176;                                        \
        float* Bs_ = smem + 8704 + s_ * 2176;                                 \
        long long ko_ = (long long)(kit) * aStep;                             \
        long long kb_ = (long long)(kit) * bStep;                             \
        cp_async16(smem_u32(As_ + aS0), aP0 + ko_);                           \
        cp_async16(smem_u32(As_ + aS1), aP1 + ko_);                           \
        cp_async16(smem_u32(Bs_ + aS0), bP0 + kb_);                           \
        cp_async16(smem_u32(Bs_ + aS1), bP1 + kb_);                           \
        asm volatile("cp.async.commit_group;\n");                             \
    }

    float acc[4][4][4];
#pragma unroll
    for (int i = 0; i < 4; i++)
#pragma unroll
        for (int j = 0; j < 4; j++)
#pragma unroll
            for (int e = 0; e < 4; e++) acc[i][j][e] = 0.f;

    float colacc[4] = {0.f, 0.f, 0.f, 0.f};

    const int kIters = K / 16;
    ISSUEX(0)
    ISSUEX(1)
    ISSUEX(2)

    for (int kit = 0; kit < kIters; kit++) {
        int rem = kIters - 1 - kit;
        if (rem >= 2)      asm volatile("cp.async.wait_group 2;\n");
        else if (rem == 1) asm volatile("cp.async.wait_group 1;\n");
        else               asm volatile("cp.async.wait_group 0;\n");
        __syncthreads();
        if (kit + 3 < kIters) ISSUEX(kit + 3)

        const float* Ab = smem + (kit & 3) * 2176;
        const float* Bb = smem + 8704 + (kit & 3) * 2176;

        // fused column-sum: read back this thread's own staged attn elements
        {
            float4 ca0 = *(const float4*)&Ab[aS0];
            float4 ca1 = *(const float4*)&Ab[aS1];
            colacc[0] += ca0.x + ca1.x;
            colacc[1] += ca0.y + ca1.y;
            colacc[2] += ca0.z + ca1.z;
            colacc[3] += ca0.w + ca1.w;
        }

#pragma unroll
        for (int ks = 0; ks < 16; ks += 8) {
            uint32_t a[4][4], b[4][2];
#pragma unroll
            for (int i = 0; i < 4; i++) {
                int rb = wm * 64 + i * 16 + grp;
                a[i][0] = __float_as_uint(Ab[(ks + qid    ) * 136 + rb]);
                a[i][1] = __float_as_uint(Ab[(ks + qid    ) * 136 + rb + 8]);
                a[i][2] = __float_as_uint(Ab[(ks + qid + 4) * 136 + rb]);
                a[i][3] = __float_as_uint(Ab[(ks + qid + 4) * 136 + rb + 8]);
            }
#pragma unroll
            for (int j = 0; j < 4; j++) {
                int nb = wn * 32 + j * 8 + grp;
                b[j][0] = __float_as_uint(Bb[(ks + qid    ) * 136 + nb]);
                b[j][1] = __float_as_uint(Bb[(ks + qid + 4) * 136 + nb]);
            }
#pragma unroll
            for (int i = 0; i < 4; i++)
#pragma unroll
                for (int j = 0; j < 4; j++) {
                    asm volatile(
                        "mma.sync.aligned.m16n8k8.row.col.f32.tf32.tf32.f32 "
                        "{%0,%1,%2,%3}, {%4,%5,%6,%7}, {%8,%9}, {%0,%1,%2,%3};\n"
                        : "+f"(acc[i][j][0]), "+f"(acc[i][j][1]),
                          "+f"(acc[i][j][2]), "+f"(acc[i][j][3])
                        : "r"(a[i][0]), "r"(a[i][1]), "r"(a[i][2]), "r"(a[i][3]),
                          "r"(b[j][0]), "r"(b[j][1]));
                }
        }
    }
#undef ISSUEX
    __syncthreads();

    // reduce column sums -> rscale
    {
        float* red = smem;   // 8 groups x 128 columns
        red[kk * 128 + cq + 0] = colacc[0];
        red[kk * 128 + cq + 1] = colacc[1];
        red[kk * 128 + cq + 2] = colacc[2];
        red[kk * 128 + cq + 3] = colacc[3];
        __syncthreads();
        if (t < 128) {
            float s = 0.f;
#pragma unroll
            for (int gg = 0; gg < 8; gg++) s += red[gg * 128 + t];
            rsc[t] = 1.f / (1e-9f + s);
        }
        __syncthreads();
    }

    float* Cz = C + (long long)z * sC;
#pragma unroll
    for (int i = 0; i < 4; i++) {
        int r0 = m0 + wm * 64 + i * 16 + grp;
        int r1 = r0 + 8;
        float rsa = rsc[r0 - m0];
        float rsb = rsc[r1 - m0];
#pragma unroll
        for (int j = 0; j < 4; j++) {
            int c = n0 + wn * 32 + j * 8 + qid * 2;
            const float* hpz = p2 + (long long)z * sC;
            float2 o0, o1;
            o0.x = cvt1(hpz[(long long)r0 * ldc + c    ] - acc[i][j][0] * rsa);
            o0.y = cvt1(hpz[(long long)r0 * ldc + c + 1] - acc[i][j][1] * rsa);
            o1.x = cvt1(hpz[(long long)r1 * ldc + c    ] - acc[i][j][2] * rsb);
            o1.y = cvt1(hpz[(long long)r1 * ldc + c + 1] - acc[i][j][3] * rsb);
            *(float2*)&Cz[(long long)r0 * ldc + c] = o0;
            *(float2*)&Cz[(long long)r1 * ldc + c] = o1;
        }
    }
}

// ---------------- softmax over last dim; writes tf32-rounded probabilities -------
__global__ void softmax_rows(float* __restrict__ attn)
{
    __shared__ float red[256];
    float* p = attn + (long long)blockIdx.x * NN;
    const int t = threadIdx.x;
    float v[8];
    float mx = -1e30f;
#pragma unroll
    for (int i = 0; i < 8; i++) { v[i] = p[t + i*256]; mx = fmaxf(mx, v[i]); }
    red[t] = mx; __syncthreads();
    for (int s = 128; s > 0; s >>= 1) {
        if (t < s) red[t] = fmaxf(red[t], red[t + s]);
        __syncthreads();
    }
    mx = red[0]; __syncthreads();
    float sum = 0.f;
#pragma unroll
    for (int i = 0; i < 8; i++) { v[i] = __expf(v[i] - mx); sum += v[i]; }
    red[t] = sum; __syncthreads();
    for (int s = 128; s > 0; s >>= 1) {
        if (t < s) red[t] += red[t + s];
        __syncthreads();
    }
    float inv = 1.f / red[0];
#pragma unroll
    for (int i = 0; i < 8; i++) p[t + i*256] = cvt1(v[i] * inv);
}

// ==================================================================================
extern "C" void kernel_launch(void* const* d_in, const int* in_sizes, int n_in,
                              void* d_out, int out_size)
{
    const float* x   = (const float*)d_in[0];
    const float* w1  = (const float*)d_in[1];
    const float* w2  = (const float*)d_in[2];
    const float* wqk = (const float*)d_in[3];
    const float* wv  = (const float*)d_in[4];
    const float* bv  = (const float*)d_in[5];
    const float* wt  = (const float*)d_in[6];
    const float* bt  = (const float*)d_in[7];
    const float* bn1g = (const float*)d_in[8],  *bn1b = (const float*)d_in[9];
    const float* bn1m = (const float*)d_in[10], *bn1v = (const float*)d_in[11];
    const float* bn2g = (const float*)d_in[12], *bn2b = (const float*)d_in[13];
    const float* bn2m = (const float*)d_in[14], *bn2v = (const float*)d_in[15];
    const float* bn3g = (const float*)d_in[16], *bn3b = (const float*)d_in[17];
    const float* bn3m = (const float*)d_in[18], *bn3v = (const float*)d_in[19];

    float *h, *q, *v, *u, *attn, *xr, *wr, *bns, *bnh;
    cudaGetSymbolAddress((void**)&h, g_h);
    cudaGetSymbolAddress((void**)&q, g_q);
    cudaGetSymbolAddress((void**)&v, g_v);
    cudaGetSymbolAddress((void**)&u, g_u);
    cudaGetSymbolAddress((void**)&attn, g_attn);
    cudaGetSymbolAddress((void**)&xr, g_xr);
    cudaGetSymbolAddress((void**)&wr, g_wr);
    cudaGetSymbolAddress((void**)&bns, g_bnscale);
    cudaGetSymbolAddress((void**)&bnh, g_bnshift);

    float* w1r  = wr;
    float* w2r  = wr + CC*CC;
    float* wqkr = wr + 2*CC*CC;
    float* wvr  = wr + 3*CC*CC;
    float* wtr  = wr + 4*CC*CC;

    cudaFuncSetAttribute(gemm_ca<1>, cudaFuncAttributeMaxDynamicSharedMemorySize, SMEMCA);
    cudaFuncSetAttribute(gemm_ca<2>, cudaFuncAttributeMaxDynamicSharedMemorySize, SMEMCA);
    cudaFuncSetAttribute(gemm_ca<3>, cudaFuncAttributeMaxDynamicSharedMemorySize, SMEMCA);
    cudaFuncSetAttribute(gemm_ca<5>, cudaFuncAttributeMaxDynamicSharedMemorySize, SMEMCA);
    cudaFuncSetAttribute(gemm_ca<6>, cudaFuncAttributeMaxDynamicSharedMemorySize, SMEMCA);
    cudaFuncSetAttribute(gemm_xr,    cudaFuncAttributeMaxDynamicSharedMemorySize, SMEMXR);

    bn_prep<<<1, 256>>>(bn1g, bn1b, bn1m, bn1v,
                        bn2g, bn2b, bn2m, bn2v,
                        bn3g, bn3b, bn3m, bn3v, bt);

    // pre-round inputs to tf32 grid (2 launches)
    round_x<<<(MTOT*CIN/4 + 255)/256, 256>>>(xr, x, MTOT*CIN);
    round_w<<<148, 256>>>(wr, w1, w2, wqk, wv, wt);

    // h1 = cvt(relu(bn1(x @ w1^T)))   (into q as temp)
    gemm_ca<1><<<dim3(CC/128, MTOT/128, 1), 256, SMEMCA>>>(
        xr, w1r, q, CIN, CIN, CIN, CC, 0, 0, 0, bns, bnh, nullptr);

    // h = cvt(relu(bn2(h1 @ w2^T)))
    gemm_ca<1><<<dim3(CC/128, MTOT/128, 1), 256, SMEMCA>>>(
        q, w2r, h, CC, CC, CC, CC, 0, 0, 0, bns + 256, bnh + 256, nullptr);

    // q = cvt(h @ wqk^T)
    gemm_ca<3><<<dim3(CC/128, MTOT/128, 1), 256, SMEMCA>>>(
        h, wqkr, q, CC, CC, CC, CC, 0, 0, 0, nullptr, nullptr, nullptr);

    // v = cvt(h @ wv^T + bv)
    gemm_ca<2><<<dim3(CC/128, MTOT/128, 1), 256, SMEMCA>>>(
        h, wvr, v, CC, CC, CC, CC, 0, 0, 0, bv, nullptr, nullptr);

    // energy[b,i,j] = q.q  (symmetric, upper-tri pairs, raw store)
    gemm_ca<5><<<dim3(NPAIRS, 1, BB), 256, SMEMCA>>>(
        q, q, attn, CC, CC, CC, NN,
        (long long)NN*CC, (long long)NN*CC, (long long)NN*NN,
        nullptr, nullptr, nullptr);

    // row softmax (writes tf32-rounded probabilities)
    softmax_rows<<<MTOT, 256>>>(attn);

    // u = cvt(h - attn^T @ v * rscale)   (colsum fused in-CTA; cp.async pipeline)
    gemm_xr<<<dim3(CC/128, NN/128, BB), 256, SMEMXR>>>(
        attn, v, u, NN, NN, CC, CC,
        (long long)NN*NN, (long long)NN*CC, (long long)NN*CC, h);

    // out[b,c,i] = h + relu(bn3(u @ wt^T + bt))   (fused, transposed store)
    gemm_ca<6><<<dim3(CC/128, MTOT/128, 1), 256, SMEMCA>>>(
        u, wtr, (float*)d_out, CC, CC, CC, CC, 0, 0, 0, bns + 512, bnh + 512, h);
}